// round 6
// baseline (speedup 1.0000x reference)
#include <cuda_runtime.h>
#include <cuda_bf16.h>
#include <math.h>

#define DIN 1024
#define D   256
#define DG  128
#define DB  64
#define NL1 8
#define NL2 32
#define BATCH 16
#define TLEN 2048
#define MROWS (BATCH*TLEN)

__device__ float g_U[MROWS*D];
__device__ float g_gin[BATCH*DIN];
__device__ int   g_idx1[BATCH];
__device__ float g_Wc[DB*D];
__device__ float g_bc[DB];
__device__ float g_nck[NL1*NL2*DB];
__device__ float g_snck[NL1*NL2];
__device__ float g_Mall[NL1*D*NL2];
__device__ float g_dall[NL1*NL2];
__device__ float g_table[NL1*NL2*D];
__device__ float g_Wl1T[DIN*D];
__device__ float g_Wg1T[DIN*D];
__device__ float g_Wg2T[D*DG];
__device__ float g_WpT[DG*DG];
__device__ float g_WfbT[DB*D];
__device__ float g_WfT[(D+DG)*D];
__device__ float g_part[2*BATCH*4*DIN];
__device__ int g_rcount;
__device__ int g_rlist[MROWS];
// pre-split bf16 operands
__device__ __nv_bfloat16 g_Xh[MROWS*DIN];
__device__ __nv_bfloat16 g_Xl[MROWS*DIN];
__device__ __nv_bfloat16 g_Wh[D*DIN];
__device__ __nv_bfloat16 g_Wlo[D*DIN];

__device__ __forceinline__ void blockLN256(float v, int tid, float* sred,
                                           float& mean, float& rinv) {
    __syncthreads();
    float s = v, q = v*v;
#pragma unroll
    for (int off = 16; off; off >>= 1) {
        s += __shfl_xor_sync(0xffffffffu, s, off);
        q += __shfl_xor_sync(0xffffffffu, q, off);
    }
    if ((tid & 31) == 0) { sred[tid >> 5] = s; sred[8 + (tid >> 5)] = q; }
    __syncthreads();
    float ts = 0.f, tq = 0.f;
#pragma unroll
    for (int w = 0; w < 8; w++) { ts += sred[w]; tq += sred[8 + w]; }
    mean = ts * (1.f / 256.f);
    float var = tq * (1.f / 256.f) - mean * mean;
    rinv = rsqrtf(fmaxf(var, 0.f) + 1e-5f);
}

__global__ void k_init() { if (threadIdx.x == 0) g_rcount = 0; }

// split fp32 -> bf16 hi/lo, vectorized
__global__ void k_cvt(const float* __restrict__ in, __nv_bfloat16* __restrict__ hi,
                      __nv_bfloat16* __restrict__ lo, int n4) {
    int stride = gridDim.x * blockDim.x;
    for (int i = blockIdx.x * blockDim.x + threadIdx.x; i < n4; i += stride) {
        float4 v = ((const float4*)in)[i];
        __nv_bfloat16 h0 = __float2bfloat16(v.x);
        __nv_bfloat16 h1 = __float2bfloat16(v.y);
        __nv_bfloat16 h2 = __float2bfloat16(v.z);
        __nv_bfloat16 h3 = __float2bfloat16(v.w);
        __nv_bfloat162* ph = (__nv_bfloat162*)hi;
        __nv_bfloat162* pl = (__nv_bfloat162*)lo;
        ph[2*i]   = __nv_bfloat162(h0, h1);
        ph[2*i+1] = __nv_bfloat162(h2, h3);
        pl[2*i]   = __nv_bfloat162(__float2bfloat16(v.x - __bfloat162float(h0)),
                                   __float2bfloat16(v.y - __bfloat162float(h1)));
        pl[2*i+1] = __nv_bfloat162(__float2bfloat16(v.z - __bfloat162float(h2)),
                                   __float2bfloat16(v.w - __bfloat162float(h3)));
    }
}

__global__ void k_transpose(const float* __restrict__ in, float* __restrict__ out,
                            int R, int C) {
    __shared__ float t[32][33];
    int cb = blockIdx.x * 32, rb = blockIdx.y * 32;
    int x = cb + threadIdx.x;
#pragma unroll
    for (int j = 0; j < 32; j += 8) {
        int r = rb + threadIdx.y + j;
        t[threadIdx.y + j][threadIdx.x] = in[(size_t)r * C + x];
    }
    __syncthreads();
    int ox = rb + threadIdx.x;
#pragma unroll
    for (int j = 0; j < 32; j += 8) {
        int c = cb + threadIdx.y + j;
        out[(size_t)c * R + ox] = t[threadIdx.x][threadIdx.y + j];
    }
}

__global__ void k_wc(const float* __restrict__ Wtb, const float* __restrict__ Wl2,
                     const float* __restrict__ bl2, const float* __restrict__ btb) {
    __shared__ float sw[D];
    int i = blockIdx.x, j = threadIdx.x;
    sw[j] = Wtb[i*D + j];
    __syncthreads();
    float acc = 0.f;
#pragma unroll 4
    for (int r = 0; r < D; r++) acc += sw[r] * Wl2[r*D + j];
    g_Wc[i*D + j] = acc;
    if (j == 0) {
        float a = btb[i];
        for (int r = 0; r < D; r++) a += sw[r] * bl2[r];
        g_bc[i] = a;
    }
}

__global__ void k_nck(const float* __restrict__ cb2) {
    __shared__ float sred[4];
    int bk = blockIdx.x, t = threadIdx.x;
    float v = cb2[bk*DB + t];
    float q = v*v;
#pragma unroll
    for (int off = 16; off; off >>= 1) q += __shfl_xor_sync(0xffffffffu, q, off);
    if ((t & 31) == 0) sred[t >> 5] = q;
    __syncthreads();
    float nrm = sqrtf(sred[0] + sred[1]);
    float nv = v / fmaxf(nrm, 1e-12f);
    g_nck[bk*DB + t] = nv;
    float s = nv;
#pragma unroll
    for (int off = 16; off; off >>= 1) s += __shfl_xor_sync(0xffffffffu, s, off);
    if ((t & 31) == 0) sred[2 + (t >> 5)] = s;
    __syncthreads();
    if (t == 0) g_snck[bk] = sred[2] + sred[3];
}

__global__ void k_Md() {
    __shared__ float sN[NL2*65];
    int i = blockIdx.x, tid = threadIdx.x;
    int k = tid & 31, cl = tid >> 5;
    int c = blockIdx.y * 8 + cl;
    for (int t = tid; t < NL2*DB; t += 256) {
        int kk = t / DB, rr = t % DB;
        sN[kk*65 + rr] = g_nck[i*NL2*DB + t];
    }
    __syncthreads();
    float acc = 0.f, cs = 0.f;
#pragma unroll 4
    for (int r = 0; r < DB; r++) {
        float wv = g_Wc[r*D + c];
        acc += wv * sN[k*65 + r];
        cs  += wv;
    }
    float sn = g_snck[i*NL2 + k];
    g_Mall[i*(D*NL2) + c*NL2 + k] = acc - cs * sn * (1.f/DB);
    if (blockIdx.y == 0 && cl == 0) {
        float dv = 0.f, bs = 0.f;
        for (int r = 0; r < DB; r++) {
            float b = g_bc[r];
            dv += b * sN[k*65 + r];
            bs += b;
        }
        g_dall[i*NL2 + k] = dv - bs * (1.f/DB) * sn;
    }
}

__global__ void k_table(const float* __restrict__ cb2, const float* __restrict__ bfb,
                        const float* __restrict__ cb1, const float* __restrict__ bf) {
    __shared__ float se[DB];
    __shared__ float sl[D];
    __shared__ float sc1[DG];
    __shared__ float sred[16];
    int bid = blockIdx.x;
    int i = bid >> 5;
    int j = threadIdx.x;
    if (j < DB) se[j] = cb2[bid*DB + j];
    if (j >= 128) sc1[j - 128] = cb1[i*DG + (j - 128)];
    __syncthreads();
    float a = bfb[j];
#pragma unroll 4
    for (int r = 0; r < DB; r++) a += se[r] * g_WfbT[r*D + j];
    float mean, rinv;
    blockLN256(a, j, sred, mean, rinv);
    sl[j] = (a - mean) * rinv;
    __syncthreads();
    float o = bf[j];
#pragma unroll 4
    for (int r = 0; r < D; r++) o += sl[r] * g_WfT[r*D + j];
#pragma unroll 4
    for (int r = 0; r < DG; r++) o += sc1[r] * g_WfT[(D + r)*D + j];
    blockLN256(o, j, sred, mean, rinv);
    g_table[bid*D + j] = fmaxf((o - mean) * rinv, 0.f);
}

__global__ void k_gs1(const float* __restrict__ x) {
    int bx = blockIdx.x;
    int b = bx >> 4, dc = (bx >> 2) & 3, tc = bx & 3;
    int d = dc * 256 + threadIdx.x;
    const float* p = x + ((size_t)b * TLEN + tc * 512) * DIN + d;
    float s = 0.f, q = 0.f;
    for (int t = 0; t < 512; t++) {
        float v = p[(size_t)t * DIN];
        s += v; q += v * v;
    }
    g_part[(b*4 + tc)*DIN + d] = s;
    g_part[BATCH*4*DIN + (b*4 + tc)*DIN + d] = q;
}

__global__ void k_gs2() {
    int b = blockIdx.x >> 2, dc = blockIdx.x & 3;
    int d = dc * 256 + threadIdx.x;
    float s = 0.f, q = 0.f;
#pragma unroll
    for (int tc = 0; tc < 4; tc++) {
        s += g_part[(b*4 + tc)*DIN + d];
        q += g_part[BATCH*4*DIN + (b*4 + tc)*DIN + d];
    }
    float mean = s * (1.f / TLEN);
    float var = (q - s * s * (1.f / TLEN)) * (1.f / (TLEN - 1));
    g_gin[b*DIN + d] = mean + sqrtf(fmaxf(var, 0.f));
}

__global__ void k_global(const float* __restrict__ bg1, const float* __restrict__ bg2,
                         const float* __restrict__ bp,  const float* __restrict__ cb1) {
    __shared__ float sg[DIN];
    __shared__ float sh[D];
    __shared__ float sgp[DG];
    __shared__ float sz[DG];
    __shared__ float sred[16];
    __shared__ float slog[NL1];
    int b = blockIdx.x, j = threadIdx.x;
    for (int t = j; t < DIN; t += 256) sg[t] = g_gin[b*DIN + t];
    __syncthreads();
    float a = bg1[j];
#pragma unroll 4
    for (int r = 0; r < DIN; r++) a += sg[r] * g_Wg1T[r*D + j];
    float mean, rinv;
    blockLN256(a, j, sred, mean, rinv);
    sh[j] = fmaxf((a - mean) * rinv, 0.f);
    __syncthreads();
    if (j < DG) {
        float g2 = bg2[j];
#pragma unroll 4
        for (int r = 0; r < D; r++) g2 += sh[r] * g_Wg2T[r*DG + j];
        sgp[j] = g2;
    }
    __syncthreads();
    if (j < DG) {
        float z = bp[j];
#pragma unroll 4
        for (int r = 0; r < DG; r++) z += sgp[r] * g_WpT[r*DG + j];
        sz[j] = z;
    }
    __syncthreads();
    {
        float zv = (j < DG) ? sz[j] : 0.f;
        float s = zv;
#pragma unroll
        for (int off = 16; off; off >>= 1) s += __shfl_xor_sync(0xffffffffu, s, off);
        if ((j & 31) == 0) sred[j >> 5] = s;
        __syncthreads();
    }
    float meanz = (sred[0]+sred[1]+sred[2]+sred[3]+sred[4]+sred[5]+sred[6]+sred[7]) * (1.f/DG);
    if (j < NL1) {
        float dz = 0.f, cs = 0.f, nn = 0.f;
        const float* cr = cb1 + j*DG;
        for (int r = 0; r < DG; r++) {
            float cv = cr[r];
            dz += sz[r]*cv; cs += cv; nn += cv*cv;
        }
        slog[j] = (dz - meanz*cs) / fmaxf(sqrtf(nn), 1e-12f);
    }
    __syncthreads();
    if (j == 0) {
        float best = slog[0]; int bi = 0;
        for (int t = 1; t < NL1; t++) if (slog[t] > best) { best = slog[t]; bi = t; }
        g_idx1[b] = bi;
    }
}

// ---------------- bf16 tensor-core GEMM with cp.async, no in-loop conversion --------
__device__ __forceinline__ void ldsm4a(unsigned* r, const __nv_bfloat16* p) {
    unsigned a = (unsigned)__cvta_generic_to_shared(p);
    asm volatile("ldmatrix.sync.aligned.m8n8.x4.shared.b16 {%0,%1,%2,%3}, [%4];\n"
        : "=r"(r[0]), "=r"(r[1]), "=r"(r[2]), "=r"(r[3]) : "r"(a));
}
__device__ __forceinline__ void mma16816(float* c, const unsigned* a, unsigned b0, unsigned b1) {
    asm volatile("mma.sync.aligned.m16n8k16.row.col.f32.bf16.bf16.f32 "
        "{%0,%1,%2,%3},{%4,%5,%6,%7},{%8,%9},{%0,%1,%2,%3};\n"
        : "+f"(c[0]), "+f"(c[1]), "+f"(c[2]), "+f"(c[3])
        : "r"(a[0]), "r"(a[1]), "r"(a[2]), "r"(a[3]), "r"(b0), "r"(b1));
}
#define CP16(dst, src) asm volatile("cp.async.cg.shared.global [%0], [%1], 16;\n" :: "r"(dst), "l"(src))
#define CPCOMMIT() asm volatile("cp.async.commit_group;\n")

#define SMA 40
// stage layout (bf16 units): Ah 0, Al 5120, Bh 10240, Bl 15360 ; stage = 20480 bf16 (40960 B)

__global__ __launch_bounds__(256)
void k_gemm(const float* __restrict__ bias) {
    extern __shared__ __align__(16) __nv_bfloat16 sm[];
    unsigned smb = (unsigned)__cvta_generic_to_shared(sm);
    int tid = threadIdx.x, lane = tid & 31, wid = tid >> 5;
    int wm = wid >> 1, wn = wid & 1;
    size_t ar0 = (size_t)blockIdx.y * 128;
    size_t br0 = (size_t)blockIdx.x * 128;

    float acc[2][8][4];
#pragma unroll
    for (int m = 0; m < 2; m++)
#pragma unroll
        for (int n = 0; n < 8; n++)
#pragma unroll
            for (int e = 0; e < 4; e++) acc[m][n][e] = 0.f;

    // issue stage kt into buffer buf
#define ISSUE(kt, buf) do {                                                     \
    unsigned sb = smb + (buf) * 40960u;                                         \
    int ko = (kt) * 32;                                                         \
    _Pragma("unroll")                                                           \
    for (int h = 0; h < 2; h++) {                                               \
        int c = tid + h * 256;                                                  \
        int row = c >> 2, slot = c & 3;                                         \
        unsigned dofs = (unsigned)(row * SMA + slot * 8) * 2u;                  \
        size_t go = (size_t)row * DIN + ko + slot * 8;                          \
        CP16(sb + dofs,          g_Xh + ar0 * DIN + go);                        \
        CP16(sb + 10240u + dofs, g_Xl + ar0 * DIN + go);                        \
        CP16(sb + 20480u + dofs, g_Wh + br0 * DIN + go);                        \
        CP16(sb + 30720u + dofs, g_Wlo + br0 * DIN + go);                       \
    }                                                                           \
    CPCOMMIT();                                                                 \
} while (0)

    ISSUE(0, 0);
    for (int kt = 0; kt < 32; kt++) {
        if (kt < 31) {
            ISSUE(kt + 1, (kt + 1) & 1);
            asm volatile("cp.async.wait_group 1;\n");
        } else {
            asm volatile("cp.async.wait_group 0;\n");
        }
        __syncthreads();
        const __nv_bfloat16* Ah = sm + (kt & 1) * 20480;
        const __nv_bfloat16* Al = Ah + 5120;
        const __nv_bfloat16* Bh = Ah + 10240;
        const __nv_bfloat16* Bl = Ah + 15360;
#pragma unroll
        for (int k16 = 0; k16 < 2; k16++) {
            int col = k16 * 16 + (lane >> 4) * 8;
            int arw = wm * 32 + (lane & 15);
            unsigned ah[2][4], al[2][4], bh[4][4], bl[4][4];
            ldsm4a(ah[0], Ah + arw * SMA + col);
            ldsm4a(ah[1], Ah + (arw + 16) * SMA + col);
            ldsm4a(al[0], Al + arw * SMA + col);
            ldsm4a(al[1], Al + (arw + 16) * SMA + col);
#pragma unroll
            for (int nb = 0; nb < 4; nb++) {
                int brw = wn * 64 + nb * 16 + (lane & 15);
                ldsm4a(bh[nb], Bh + brw * SMA + col);
                ldsm4a(bl[nb], Bl + brw * SMA + col);
            }
#pragma unroll
            for (int m = 0; m < 2; m++)
#pragma unroll
                for (int nt = 0; nt < 8; nt++) {
                    int nb = nt >> 1, o = nt & 1;
                    mma16816(acc[m][nt], ah[m], bh[nb][o], bh[nb][o + 2]);
                    mma16816(acc[m][nt], ah[m], bl[nb][o], bl[nb][o + 2]);
                    mma16816(acc[m][nt], al[m], bh[nb][o], bh[nb][o + 2]);
                }
        }
        __syncthreads();
    }
    int row0 = (int)ar0 + wm * 32 + (lane >> 2);
    int col0 = (int)br0 + wn * 64 + 2 * (lane & 3);
#pragma unroll
    for (int m = 0; m < 2; m++)
#pragma unroll
        for (int nt = 0; nt < 8; nt++) {
            int cg = col0 + nt * 8;
            float b0 = bias[cg], b1 = bias[cg + 1];
            int r0 = row0 + m * 16;
            *(float2*)(g_U + (size_t)r0 * D + cg) =
                make_float2(acc[m][nt][0] + b0, acc[m][nt][1] + b1);
            *(float2*)(g_U + (size_t)(r0 + 8) * D + cg) =
                make_float2(acc[m][nt][2] + b0, acc[m][nt][3] + b1);
        }
#undef ISSUE
}

__global__ __launch_bounds__(256)
void k_epilogue(float* __restrict__ out) {
    __shared__ float sM[D * NL2];
    __shared__ float sd[NL2];
    __shared__ int si1;
    int b = blockIdx.x;
    int tid = threadIdx.x;
    int lane = tid & 31;
    int w = tid >> 5;
    if (tid == 0) si1 = g_idx1[b];
    __syncthreads();
    int i1 = si1;
    {
        const float4* src = (const float4*)(g_Mall + (size_t)i1 * D * NL2);
        float4* dst = (float4*)sM;
        for (int t = tid; t < D * NL2 / 4; t += 256) dst[t] = src[t];
        if (tid < NL2) sd[tid] = g_dall[i1 * NL2 + tid];
    }
    __syncthreads();
    int rowBase = b * TLEN + blockIdx.y * 128 + w * 16;
    for (int r = 0; r < 16; r++) {
        int row = rowBase + r;
        const float4* up = (const float4*)(g_U + (size_t)row * D);
        float4 u0 = up[lane];
        float4 u1 = up[lane + 32];
        float h[8] = {u0.x, u0.y, u0.z, u0.w, u1.x, u1.y, u1.z, u1.w};
        float s = 0.f, q = 0.f;
#pragma unroll
        for (int e = 0; e < 8; e++) { s += h[e]; q += h[e]*h[e]; }
#pragma unroll
        for (int off = 16; off; off >>= 1) {
            s += __shfl_xor_sync(0xffffffffu, s, off);
            q += __shfl_xor_sync(0xffffffffu, q, off);
        }
        float mean = s * (1.f / 256.f);
        float var = q * (1.f / 256.f) - mean * mean;
        float rinv = rsqrtf(fmaxf(var, 0.f) + 1e-5f);
#pragma unroll
        for (int e = 0; e < 8; e++) h[e] = fmaxf((h[e] - mean) * rinv, 0.f);
        float acc = sd[lane];
#pragma unroll
        for (int e = 0; e < 8; e++) {
            int cb = (e < 4) ? e : (e + 124);
#pragma unroll 8
            for (int srcl = 0; srcl < 32; srcl++) {
                float hv = __shfl_sync(0xffffffffu, h[e], srcl);
                acc += hv * sM[(srcl * 4 + cb) * NL2 + lane];
            }
        }
        float best = acc; int bidx = lane;
#pragma unroll
        for (int off = 16; off; off >>= 1) {
            float ov = __shfl_xor_sync(0xffffffffu, best, off);
            int   oi = __shfl_xor_sync(0xffffffffu, bidx, off);
            if (ov > best || (ov == best && oi < bidx)) { best = ov; bidx = oi; }
        }
        float second = (lane == bidx) ? -1e30f : acc;
#pragma unroll
        for (int off = 16; off; off >>= 1)
            second = fmaxf(second, __shfl_xor_sync(0xffffffffu, second, off));
        if (lane == 0 && (best - second) < 0.01f * fmaxf(1.f, fabsf(best))) {
            int p = atomicAdd(&g_rcount, 1);
            g_rlist[p] = row;
        }
        const float4* trow = (const float4*)(g_table + (size_t)(i1 * NL2 + bidx) * D);
        float4* orow = (float4*)(out + (size_t)row * D);
        orow[lane]      = trow[lane];
        orow[lane + 32] = trow[lane + 32];
    }
}

__global__ __launch_bounds__(256)
void k_repair(const float* __restrict__ x, const float* __restrict__ bl1,
              float* __restrict__ out) {
    __shared__ float xs[8][DIN];
    __shared__ float hs[8][D + 1];
    __shared__ int rows[8];
    __shared__ float sred[16];
    int tid = threadIdx.x, lane = tid & 31, w = tid >> 5;
    int total = g_rcount;
    for (int base = blockIdx.x * 8; base < total; base += gridDim.x * 8) {
        int cnt = min(8, total - base);
        __syncthreads();
        if (tid < 8) rows[tid] = (tid < cnt) ? g_rlist[base + tid] : g_rlist[base];
        __syncthreads();
#pragma unroll
        for (int i = 0; i < 8; i++) {
            const float4* src = (const float4*)(x + (size_t)rows[i] * DIN);
            float4* dst = (float4*)xs[i];
            if (tid < DIN/4) dst[tid] = src[tid];
        }
        __syncthreads();
        float a[8];
#pragma unroll
        for (int i = 0; i < 8; i++) a[i] = 0.f;
        for (int r = 0; r < DIN; r++) {
            float wv = g_Wl1T[r*D + tid];
#pragma unroll
            for (int i = 0; i < 8; i++) a[i] += xs[i][r] * wv;
        }
        float bl = bl1[tid];
#pragma unroll
        for (int i = 0; i < 8; i++) {
            float v = a[i] + bl;
            float mean, rinv;
            blockLN256(v, tid, sred, mean, rinv);
            hs[i][tid] = fmaxf((v - mean) * rinv, 0.f);
        }
        __syncthreads();
        if (w < cnt) {
            int row = rows[w];
            int i1 = g_idx1[row / TLEN];
            float acc = g_dall[i1*NL2 + lane];
            const float* M = g_Mall + (size_t)i1 * D * NL2;
            for (int c = 0; c < D; c++) acc += hs[w][c] * M[c*NL2 + lane];
            float best = acc; int bidx = lane;
#pragma unroll
            for (int off = 16; off; off >>= 1) {
                float ov = __shfl_xor_sync(0xffffffffu, best, off);
                int   oi = __shfl_xor_sync(0xffffffffu, bidx, off);
                if (ov > best || (ov == best && oi < bidx)) { best = ov; bidx = oi; }
            }
            const float4* trow = (const float4*)(g_table + (size_t)(i1*NL2 + bidx) * D);
            float4* orow = (float4*)(out + (size_t)row * D);
#pragma unroll
            for (int e = 0; e < 2; e++) orow[lane + e*32] = trow[lane + e*32];
        }
        __syncthreads();
    }
}

extern "C" void kernel_launch(void* const* d_in, const int* in_sizes, int n_in,
                              void* d_out, int out_size) {
    const float* x   = (const float*)d_in[0];
    const float* Wg1 = (const float*)d_in[1];
    const float* bg1 = (const float*)d_in[2];
    const float* Wg2 = (const float*)d_in[3];
    const float* bg2 = (const float*)d_in[4];
    const float* Wl1 = (const float*)d_in[5];
    const float* bl1 = (const float*)d_in[6];
    const float* Wl2 = (const float*)d_in[7];
    const float* bl2 = (const float*)d_in[8];
    const float* Wp  = (const float*)d_in[9];
    const float* bp  = (const float*)d_in[10];
    const float* cb1 = (const float*)d_in[11];
    const float* Wtb = (const float*)d_in[12];
    const float* btb = (const float*)d_in[13];
    const float* Wfb = (const float*)d_in[14];
    const float* bfb = (const float*)d_in[15];
    const float* cb2 = (const float*)d_in[16];
    const float* Wf  = (const float*)d_in[17];
    const float* bf  = (const float*)d_in[18];
    float* out = (float*)d_out;

    static int smem_set = 0;
    if (!smem_set) {
        cudaFuncSetAttribute(k_gemm, cudaFuncAttributeMaxDynamicSharedMemorySize, 81920);
        smem_set = 1;
    }

    float *dWl1T, *dWg1T, *dWg2T, *dWpT, *dWfbT, *dWfT;
    __nv_bfloat16 *dXh, *dXl, *dWh, *dWlo;
    cudaGetSymbolAddress((void**)&dWl1T, g_Wl1T);
    cudaGetSymbolAddress((void**)&dWg1T, g_Wg1T);
    cudaGetSymbolAddress((void**)&dWg2T, g_Wg2T);
    cudaGetSymbolAddress((void**)&dWpT,  g_WpT);
    cudaGetSymbolAddress((void**)&dWfbT, g_WfbT);
    cudaGetSymbolAddress((void**)&dWfT,  g_WfT);
    cudaGetSymbolAddress((void**)&dXh, g_Xh);
    cudaGetSymbolAddress((void**)&dXl, g_Xl);
    cudaGetSymbolAddress((void**)&dWh, g_Wh);
    cudaGetSymbolAddress((void**)&dWlo, g_Wlo);

    k_init<<<1, 32>>>();
    k_cvt<<<4096, 256>>>(x, dXh, dXl, MROWS*DIN/4);
    k_cvt<<<256, 256>>>(Wl1, dWh, dWlo, D*DIN/4);
    dim3 tb(32, 8);
    k_transpose<<<dim3(DIN/32, D/32), tb>>>(Wl1, dWl1T, D, DIN);
    k_transpose<<<dim3(DIN/32, D/32), tb>>>(Wg1, dWg1T, D, DIN);
    k_transpose<<<dim3(D/32, DG/32), tb>>>(Wg2, dWg2T, DG, D);
    k_transpose<<<dim3(DG/32, DG/32), tb>>>(Wp, dWpT, DG, DG);
    k_transpose<<<dim3(DB/32, D/32), tb>>>(Wfb, dWfbT, D, DB);
    k_transpose<<<dim3((D+DG)/32, D/32), tb>>>(Wf, dWfT, D, D+DG);
    k_wc   <<<64, 256>>>(Wtb, Wl2, bl2, btb);
    k_nck  <<<256, 64>>>(cb2);
    k_Md   <<<dim3(8, 32), 256>>>();
    k_table<<<256, 256>>>(cb2, bfb, cb1, bf);
    k_gs1  <<<256, 256>>>(x);
    k_gs2  <<<64, 256>>>();
    k_global<<<16, 256>>>(bg1, bg2, bp, cb1);
    k_gemm <<<dim3(2, 256), 256, 81920>>>(bl1);
    k_epilogue<<<dim3(16, 16), 256>>>(out);
    k_repair<<<148, 256>>>(x, bl1, out);
}

// round 10
// speedup vs baseline: 1.4129x; 1.4129x over previous
#include <cuda_runtime.h>
#include <cuda_bf16.h>
#include <math.h>

typedef unsigned long long u64;

#define DIN 1024
#define D   256
#define DG  128
#define DB  64
#define NL1 8
#define NL2 32
#define BATCH 16
#define TLEN 2048
#define MROWS (BATCH*TLEN)

__device__ float g_U[MROWS*D];
__device__ float g_gin[BATCH*DIN];
__device__ int   g_idx1[BATCH];
__device__ float g_Wc[DB*D];
__device__ float g_bc[DB];
__device__ float g_nck[NL1*NL2*DB];
__device__ float g_snck[NL1*NL2];
__device__ float g_Mall[NL1*D*NL2];
__device__ float g_dall[NL1*NL2];
__device__ float g_table[NL1*NL2*D];
__device__ float g_Wg1T[DIN*D];
__device__ float g_Wg2T[D*DG];
__device__ float g_WpT[DG*DG];
__device__ float g_WfbT[DB*D];
__device__ float g_WfT[(D+DG)*D];
__device__ float g_part[2*BATCH*4*DIN];

__device__ __forceinline__ void blockLN256(float v, int tid, float* sred,
                                           float& mean, float& rinv) {
    __syncthreads();
    float s = v, q = v*v;
#pragma unroll
    for (int off = 16; off; off >>= 1) {
        s += __shfl_xor_sync(0xffffffffu, s, off);
        q += __shfl_xor_sync(0xffffffffu, q, off);
    }
    if ((tid & 31) == 0) { sred[tid >> 5] = s; sred[8 + (tid >> 5)] = q; }
    __syncthreads();
    float ts = 0.f, tq = 0.f;
#pragma unroll
    for (int w = 0; w < 8; w++) { ts += sred[w]; tq += sred[8 + w]; }
    mean = ts * (1.f / 256.f);
    float var = tq * (1.f / 256.f) - mean * mean;
    rinv = rsqrtf(fmaxf(var, 0.f) + 1e-5f);
}

__global__ void k_transpose(const float* __restrict__ in, float* __restrict__ out,
                            int R, int C) {
    __shared__ float t[32][33];
    int cb = blockIdx.x * 32, rb = blockIdx.y * 32;
    int x = cb + threadIdx.x;
#pragma unroll
    for (int j = 0; j < 32; j += 8) {
        int r = rb + threadIdx.y + j;
        t[threadIdx.y + j][threadIdx.x] = in[(size_t)r * C + x];
    }
    __syncthreads();
    int ox = rb + threadIdx.x;
#pragma unroll
    for (int j = 0; j < 32; j += 8) {
        int c = cb + threadIdx.y + j;
        out[(size_t)c * R + ox] = t[threadIdx.x][threadIdx.y + j];
    }
}

__global__ void k_wc(const float* __restrict__ Wtb, const float* __restrict__ Wl2,
                     const float* __restrict__ bl2, const float* __restrict__ btb) {
    __shared__ float sw[D];
    int i = blockIdx.x, j = threadIdx.x;
    sw[j] = Wtb[i*D + j];
    __syncthreads();
    float acc = 0.f;
#pragma unroll 4
    for (int r = 0; r < D; r++) acc += sw[r] * Wl2[r*D + j];
    g_Wc[i*D + j] = acc;
    if (j == 0) {
        float a = btb[i];
        for (int r = 0; r < D; r++) a += sw[r] * bl2[r];
        g_bc[i] = a;
    }
}

__global__ void k_nck(const float* __restrict__ cb2) {
    __shared__ float sred[4];
    int bk = blockIdx.x, t = threadIdx.x;
    float v = cb2[bk*DB + t];
    float q = v*v;
#pragma unroll
    for (int off = 16; off; off >>= 1) q += __shfl_xor_sync(0xffffffffu, q, off);
    if ((t & 31) == 0) sred[t >> 5] = q;
    __syncthreads();
    float nrm = sqrtf(sred[0] + sred[1]);
    float nv = v / fmaxf(nrm, 1e-12f);
    g_nck[bk*DB + t] = nv;
    float s = nv;
#pragma unroll
    for (int off = 16; off; off >>= 1) s += __shfl_xor_sync(0xffffffffu, s, off);
    if ((t & 31) == 0) sred[2 + (t >> 5)] = s;
    __syncthreads();
    if (t == 0) g_snck[bk] = sred[2] + sred[3];
}

__global__ void k_Md() {
    __shared__ float sN[NL2*65];
    int i = blockIdx.x, tid = threadIdx.x;
    int k = tid & 31, cl = tid >> 5;
    int c = blockIdx.y * 8 + cl;
    for (int t = tid; t < NL2*DB; t += 256) {
        int kk = t / DB, rr = t % DB;
        sN[kk*65 + rr] = g_nck[i*NL2*DB + t];
    }
    __syncthreads();
    float acc = 0.f, cs = 0.f;
#pragma unroll 4
    for (int r = 0; r < DB; r++) {
        float wv = g_Wc[r*D + c];
        acc += wv * sN[k*65 + r];
        cs  += wv;
    }
    float sn = g_snck[i*NL2 + k];
    g_Mall[i*(D*NL2) + c*NL2 + k] = acc - cs * sn * (1.f/DB);
    if (blockIdx.y == 0 && cl == 0) {
        float dv = 0.f, bs = 0.f;
        for (int r = 0; r < DB; r++) {
            float b = g_bc[r];
            dv += b * sN[k*65 + r];
            bs += b;
        }
        g_dall[i*NL2 + k] = dv - bs * (1.f/DB) * sn;
    }
}

__global__ void k_table(const float* __restrict__ cb2, const float* __restrict__ bfb,
                        const float* __restrict__ cb1, const float* __restrict__ bf) {
    __shared__ float se[DB];
    __shared__ float sl[D];
    __shared__ float sc1[DG];
    __shared__ float sred[16];
    int bid = blockIdx.x;
    int i = bid >> 5;
    int j = threadIdx.x;
    if (j < DB) se[j] = cb2[bid*DB + j];
    if (j >= 128) sc1[j - 128] = cb1[i*DG + (j - 128)];
    __syncthreads();
    float a = bfb[j];
#pragma unroll 4
    for (int r = 0; r < DB; r++) a += se[r] * g_WfbT[r*D + j];
    float mean, rinv;
    blockLN256(a, j, sred, mean, rinv);
    sl[j] = (a - mean) * rinv;
    __syncthreads();
    float o = bf[j];
#pragma unroll 4
    for (int r = 0; r < D; r++) o += sl[r] * g_WfT[r*D + j];
#pragma unroll 4
    for (int r = 0; r < DG; r++) o += sc1[r] * g_WfT[(D + r)*D + j];
    blockLN256(o, j, sred, mean, rinv);
    g_table[bid*D + j] = fmaxf((o - mean) * rinv, 0.f);
}

__global__ void k_gs1(const float* __restrict__ x) {
    int bx = blockIdx.x;
    int b = bx >> 4, dc = (bx >> 2) & 3, tc = bx & 3;
    int d = dc * 256 + threadIdx.x;
    const float* p = x + ((size_t)b * TLEN + tc * 512) * DIN + d;
    float s = 0.f, q = 0.f;
    for (int t = 0; t < 512; t++) {
        float v = p[(size_t)t * DIN];
        s += v; q += v * v;
    }
    g_part[(b*4 + tc)*DIN + d] = s;
    g_part[BATCH*4*DIN + (b*4 + tc)*DIN + d] = q;
}

__global__ void k_gs2() {
    int b = blockIdx.x >> 2, dc = blockIdx.x & 3;
    int d = dc * 256 + threadIdx.x;
    float s = 0.f, q = 0.f;
#pragma unroll
    for (int tc = 0; tc < 4; tc++) {
        s += g_part[(b*4 + tc)*DIN + d];
        q += g_part[BATCH*4*DIN + (b*4 + tc)*DIN + d];
    }
    float mean = s * (1.f / TLEN);
    float var = (q - s * s * (1.f / TLEN)) * (1.f / (TLEN - 1));
    g_gin[b*DIN + d] = mean + sqrtf(fmaxf(var, 0.f));
}

__global__ void k_global(const float* __restrict__ bg1, const float* __restrict__ bg2,
                         const float* __restrict__ bp,  const float* __restrict__ cb1) {
    __shared__ float sg[DIN];
    __shared__ float sh[D];
    __shared__ float sgp[DG];
    __shared__ float sz[DG];
    __shared__ float sred[16];
    __shared__ float slog[NL1];
    int b = blockIdx.x, j = threadIdx.x;
    for (int t = j; t < DIN; t += 256) sg[t] = g_gin[b*DIN + t];
    __syncthreads();
    float a = bg1[j];
#pragma unroll 4
    for (int r = 0; r < DIN; r++) a += sg[r] * g_Wg1T[r*D + j];
    float mean, rinv;
    blockLN256(a, j, sred, mean, rinv);
    sh[j] = fmaxf((a - mean) * rinv, 0.f);
    __syncthreads();
    if (j < DG) {
        float g2 = bg2[j];
#pragma unroll 4
        for (int r = 0; r < D; r++) g2 += sh[r] * g_Wg2T[r*DG + j];
        sgp[j] = g2;
    }
    __syncthreads();
    if (j < DG) {
        float z = bp[j];
#pragma unroll 4
        for (int r = 0; r < DG; r++) z += sgp[r] * g_WpT[r*DG + j];
        sz[j] = z;
    }
    __syncthreads();
    {
        float zv = (j < DG) ? sz[j] : 0.f;
        float s = zv;
#pragma unroll
        for (int off = 16; off; off >>= 1) s += __shfl_xor_sync(0xffffffffu, s, off);
        if ((j & 31) == 0) sred[j >> 5] = s;
        __syncthreads();
    }
    float meanz = (sred[0]+sred[1]+sred[2]+sred[3]+sred[4]+sred[5]+sred[6]+sred[7]) * (1.f/DG);
    if (j < NL1) {
        float dz = 0.f, cs = 0.f, nn = 0.f;
        const float* cr = cb1 + j*DG;
        for (int r = 0; r < DG; r++) {
            float cv = cr[r];
            dz += sz[r]*cv; cs += cv; nn += cv*cv;
        }
        slog[j] = (dz - meanz*cs) / fmaxf(sqrtf(nn), 1e-12f);
    }
    __syncthreads();
    if (j == 0) {
        float best = slog[0]; int bi = 0;
        for (int t = 1; t < NL1; t++) if (slog[t] > best) { best = slog[t]; bi = t; }
        g_idx1[b] = bi;
    }
}

// -------- fp32x2 packed SGEMM: u = x @ Wl1.T + bl1 --------
// M=32768, N=256, K=1024; 128x128x16 tiles, 256 thr, 8 rows x 4 col-pairs/thread
__device__ __forceinline__ void ffma2(u64& c, u64 a, u64 b) {
    asm("fma.rn.f32x2 %0, %1, %2, %0;" : "+l"(c) : "l"(a), "l"(b));
}
union F2U { u64 u; float2 f; };

__global__ __launch_bounds__(256, 2)
void k_sgemm(const float* __restrict__ A, const float* __restrict__ Bm,
             const float* __restrict__ bias) {
    __shared__ float2 As[2][16][128];   // A duplicated pairs (a,a): 32 KB
    __shared__ float  Bs[2][16][128];   // 16 KB
    const int K = DIN;
    int tid = threadIdx.x;
    int lr = tid >> 2;
    int lk = (tid & 3) << 2;
    const float* Ap = A  + (size_t)(blockIdx.y * 128) * K;
    const float* Bp = Bm + (size_t)(blockIdx.x * 128) * K;
    int tx = tid & 15, ty = tid >> 4;
    int ar0 = ty * 4, ar1 = 64 + ty * 4;
    int bc0 = tx * 4, bc1 = 64 + tx * 4;

    u64 acc[8][4];
#pragma unroll
    for (int i = 0; i < 8; i++)
#pragma unroll
        for (int p = 0; p < 4; p++) acc[i][p] = 0ULL;

    float4 ra0, ra1, rb0, rb1;
    ra0 = *(const float4*)(Ap + (size_t)lr * K + lk);
    ra1 = *(const float4*)(Ap + (size_t)(lr + 64) * K + lk);
    rb0 = *(const float4*)(Bp + (size_t)lr * K + lk);
    rb1 = *(const float4*)(Bp + (size_t)(lr + 64) * K + lk);
    As[0][lk+0][lr]    = make_float2(ra0.x, ra0.x);
    As[0][lk+1][lr]    = make_float2(ra0.y, ra0.y);
    As[0][lk+2][lr]    = make_float2(ra0.z, ra0.z);
    As[0][lk+3][lr]    = make_float2(ra0.w, ra0.w);
    As[0][lk+0][lr+64] = make_float2(ra1.x, ra1.x);
    As[0][lk+1][lr+64] = make_float2(ra1.y, ra1.y);
    As[0][lk+2][lr+64] = make_float2(ra1.z, ra1.z);
    As[0][lk+3][lr+64] = make_float2(ra1.w, ra1.w);
    Bs[0][lk+0][lr]    = rb0.x; Bs[0][lk+1][lr]    = rb0.y;
    Bs[0][lk+2][lr]    = rb0.z; Bs[0][lk+3][lr]    = rb0.w;
    Bs[0][lk+0][lr+64] = rb1.x; Bs[0][lk+1][lr+64] = rb1.y;
    Bs[0][lk+2][lr+64] = rb1.z; Bs[0][lk+3][lr+64] = rb1.w;
    __syncthreads();

    for (int kt = 0; kt < 64; kt++) {
        int cur = kt & 1;
        if (kt < 63) {
            const float* Ak = Ap + (kt + 1) * 16 + lk;
            const float* Bk = Bp + (kt + 1) * 16 + lk;
            ra0 = *(const float4*)(Ak + (size_t)lr * K);
            ra1 = *(const float4*)(Ak + (size_t)(lr + 64) * K);
            rb0 = *(const float4*)(Bk + (size_t)lr * K);
            rb1 = *(const float4*)(Bk + (size_t)(lr + 64) * K);
        }
#pragma unroll
        for (int kk = 0; kk < 16; kk++) {
            ulonglong2 a01 = *(const ulonglong2*)&As[cur][kk][ar0];
            ulonglong2 a23 = *(const ulonglong2*)&As[cur][kk][ar0 + 2];
            ulonglong2 a45 = *(const ulonglong2*)&As[cur][kk][ar1];
            ulonglong2 a67 = *(const ulonglong2*)&As[cur][kk][ar1 + 2];
            ulonglong2 b01 = *(const ulonglong2*)&Bs[cur][kk][bc0];
            ulonglong2 b23 = *(const ulonglong2*)&Bs[cur][kk][bc1];
            u64 av[8] = {a01.x, a01.y, a23.x, a23.y, a45.x, a45.y, a67.x, a67.y};
            u64 bv[4] = {b01.x, b01.y, b23.x, b23.y};
#pragma unroll
            for (int i = 0; i < 8; i++)
#pragma unroll
                for (int p = 0; p < 4; p++) ffma2(acc[i][p], av[i], bv[p]);
        }
        if (kt < 63) {
            int nxt = cur ^ 1;
            As[nxt][lk+0][lr]    = make_float2(ra0.x, ra0.x);
            As[nxt][lk+1][lr]    = make_float2(ra0.y, ra0.y);
            As[nxt][lk+2][lr]    = make_float2(ra0.z, ra0.z);
            As[nxt][lk+3][lr]    = make_float2(ra0.w, ra0.w);
            As[nxt][lk+0][lr+64] = make_float2(ra1.x, ra1.x);
            As[nxt][lk+1][lr+64] = make_float2(ra1.y, ra1.y);
            As[nxt][lk+2][lr+64] = make_float2(ra1.z, ra1.z);
            As[nxt][lk+3][lr+64] = make_float2(ra1.w, ra1.w);
            Bs[nxt][lk+0][lr]    = rb0.x; Bs[nxt][lk+1][lr]    = rb0.y;
            Bs[nxt][lk+2][lr]    = rb0.z; Bs[nxt][lk+3][lr]    = rb0.w;
            Bs[nxt][lk+0][lr+64] = rb1.x; Bs[nxt][lk+1][lr+64] = rb1.y;
            Bs[nxt][lk+2][lr+64] = rb1.z; Bs[nxt][lk+3][lr+64] = rb1.w;
            __syncthreads();
        }
    }
    int row0 = blockIdx.y * 128;
    int col0 = blockIdx.x * 128;
    float4 bA = *(const float4*)(bias + col0 + bc0);
    float4 bB = *(const float4*)(bias + col0 + bc1);
#pragma unroll
    for (int i = 0; i < 8; i++) {
        int r = row0 + ((i < 4) ? (ar0 + i) : (ar1 + i - 4));
        F2U p0, p1, p2, p3;
        p0.u = acc[i][0]; p1.u = acc[i][1]; p2.u = acc[i][2]; p3.u = acc[i][3];
        float4 v0 = make_float4(p0.f.x + bA.x, p0.f.y + bA.y,
                                p1.f.x + bA.z, p1.f.y + bA.w);
        float4 v1 = make_float4(p2.f.x + bB.x, p2.f.y + bB.y,
                                p3.f.x + bB.z, p3.f.y + bB.w);
        *(float4*)(g_U + (size_t)r * D + col0 + bc0) = v0;
        *(float4*)(g_U + (size_t)r * D + col0 + bc1) = v1;
    }
}

__global__ __launch_bounds__(256)
void k_epilogue(float* __restrict__ out) {
    __shared__ float sM[D * NL2];
    __shared__ float sd[NL2];
    __shared__ int si1;
    int b = blockIdx.x;
    int tid = threadIdx.x;
    int lane = tid & 31;
    int w = tid >> 5;
    if (tid == 0) si1 = g_idx1[b];
    __syncthreads();
    int i1 = si1;
    {
        const float4* src = (const float4*)(g_Mall + (size_t)i1 * D * NL2);
        float4* dst = (float4*)sM;
        for (int t = tid; t < D * NL2 / 4; t += 256) dst[t] = src[t];
        if (tid < NL2) sd[tid] = g_dall[i1 * NL2 + tid];
    }
    __syncthreads();
    int rowBase = b * TLEN + blockIdx.y * 128 + w * 16;
    for (int r = 0; r < 16; r++) {
        int row = rowBase + r;
        const float4* up = (const float4*)(g_U + (size_t)row * D);
        float4 u0 = up[lane];
        float4 u1 = up[lane + 32];
        float h[8] = {u0.x, u0.y, u0.z, u0.w, u1.x, u1.y, u1.z, u1.w};
        float s = 0.f, q = 0.f;
#pragma unroll
        for (int e = 0; e < 8; e++) { s += h[e]; q += h[e]*h[e]; }
#pragma unroll
        for (int off = 16; off; off >>= 1) {
            s += __shfl_xor_sync(0xffffffffu, s, off);
            q += __shfl_xor_sync(0xffffffffu, q, off);
        }
        float mean = s * (1.f / 256.f);
        float var = q * (1.f / 256.f) - mean * mean;
        float rinv = rsqrtf(fmaxf(var, 0.f) + 1e-5f);
#pragma unroll
        for (int e = 0; e < 8; e++) h[e] = fmaxf((h[e] - mean) * rinv, 0.f);
        float acc = sd[lane];
#pragma unroll
        for (int e = 0; e < 8; e++) {
            int cb = (e < 4) ? e : (e + 124);
#pragma unroll 8
            for (int srcl = 0; srcl < 32; srcl++) {
                float hv = __shfl_sync(0xffffffffu, h[e], srcl);
                acc += hv * sM[(srcl * 4 + cb) * NL2 + lane];
            }
        }
        float best = acc; int bidx = lane;
#pragma unroll
        for (int off = 16; off; off >>= 1) {
            float ov = __shfl_xor_sync(0xffffffffu, best, off);
            int   oi = __shfl_xor_sync(0xffffffffu, bidx, off);
            if (ov > best || (ov == best && oi < bidx)) { best = ov; bidx = oi; }
        }
        const float4* trow = (const float4*)(g_table + (size_t)(i1 * NL2 + bidx) * D);
        float4* orow = (float4*)(out + (size_t)row * D);
        orow[lane]      = trow[lane];
        orow[lane + 32] = trow[lane + 32];
    }
}

extern "C" void kernel_launch(void* const* d_in, const int* in_sizes, int n_in,
                              void* d_out, int out_size) {
    const float* x   = (const float*)d_in[0];
    const float* Wg1 = (const float*)d_in[1];
    const float* bg1 = (const float*)d_in[2];
    const float* Wg2 = (const float*)d_in[3];
    const float* bg2 = (const float*)d_in[4];
    const float* Wl1 = (const float*)d_in[5];
    const float* bl1 = (const float*)d_in[6];
    const float* Wl2 = (const float*)d_in[7];
    const float* bl2 = (const float*)d_in[8];
    const float* Wp  = (const float*)d_in[9];
    const float* bp  = (const float*)d_in[10];
    const float* cb1 = (const float*)d_in[11];
    const float* Wtb = (const float*)d_in[12];
    const float* btb = (const float*)d_in[13];
    const float* Wfb = (const float*)d_in[14];
    const float* bfb = (const float*)d_in[15];
    const float* cb2 = (const float*)d_in[16];
    const float* Wf  = (const float*)d_in[17];
    const float* bf  = (const float*)d_in[18];
    float* out = (float*)d_out;

    float *dWg1T, *dWg2T, *dWpT, *dWfbT, *dWfT;
    cudaGetSymbolAddress((void**)&dWg1T, g_Wg1T);
    cudaGetSymbolAddress((void**)&dWg2T, g_Wg2T);
    cudaGetSymbolAddress((void**)&dWpT,  g_WpT);
    cudaGetSymbolAddress((void**)&dWfbT, g_WfbT);
    cudaGetSymbolAddress((void**)&dWfT,  g_WfT);

    dim3 tb(32, 8);
    k_transpose<<<dim3(DIN/32, D/32), tb>>>(Wg1, dWg1T, D, DIN);
    k_transpose<<<dim3(D/32, DG/32), tb>>>(Wg2, dWg2T, DG, D);
    k_transpose<<<dim3(DG/32, DG/32), tb>>>(Wp, dWpT, DG, DG);
    k_transpose<<<dim3(DB/32, D/32), tb>>>(Wfb, dWfbT, D, DB);
    k_transpose<<<dim3((D+DG)/32, D/32), tb>>>(Wf, dWfT, D, D+DG);
    k_wc   <<<64, 256>>>(Wtb, Wl2, bl2, btb);
    k_nck  <<<256, 64>>>(cb2);
    k_Md   <<<dim3(8, 32), 256>>>();
    k_table<<<256, 256>>>(cb2, bfb, cb1, bf);
    k_gs1  <<<256, 256>>>(x);
    k_gs2  <<<64, 256>>>();
    k_global<<<16, 256>>>(bg1, bg2, bp, cb1);
    k_sgemm<<<dim3(2, 256), 256>>>(x, Wl1, bl1);
    k_epilogue<<<dim3(16, 16), 256>>>(out);
}

// round 12
// speedup vs baseline: 1.6617x; 1.1760x over previous
#include <cuda_runtime.h>
#include <cuda_bf16.h>
#include <math.h>

typedef unsigned long long u64;

#define DIN 1024
#define D   256
#define DG  128
#define DB  64
#define NL1 8
#define NL2 32
#define BATCH 16
#define TLEN 2048
#define MROWS (BATCH*TLEN)

__device__ float g_U[MROWS*D];
__device__ float g_gin[BATCH*DIN];
__device__ int   g_idx1[BATCH];
__device__ float g_Wc[DB*D];
__device__ float g_bc[DB];
__device__ float g_nck[NL1*NL2*DB];
__device__ float g_snck[NL1*NL2];
__device__ float g_Mall[NL1*D*NL2];
__device__ float g_dall[NL1*NL2];
__device__ float g_table[NL1*NL2*D];
__device__ float g_Wg1T[DIN*D];
__device__ float g_Wg2T[D*DG];
__device__ float g_WpT[DG*DG];
__device__ float g_WfbT[DB*D];
__device__ float g_WfT[(D+DG)*D];
__device__ float g_part[2*BATCH*4*DIN];

__device__ __forceinline__ void blockLN256(float v, int tid, float* sred,
                                           float& mean, float& rinv) {
    __syncthreads();
    float s = v, q = v*v;
#pragma unroll
    for (int off = 16; off; off >>= 1) {
        s += __shfl_xor_sync(0xffffffffu, s, off);
        q += __shfl_xor_sync(0xffffffffu, q, off);
    }
    if ((tid & 31) == 0) { sred[tid >> 5] = s; sred[8 + (tid >> 5)] = q; }
    __syncthreads();
    float ts = 0.f, tq = 0.f;
#pragma unroll
    for (int w = 0; w < 8; w++) { ts += sred[w]; tq += sred[8 + w]; }
    mean = ts * (1.f / 256.f);
    float var = tq * (1.f / 256.f) - mean * mean;
    rinv = rsqrtf(fmaxf(var, 0.f) + 1e-5f);
}

// all 5 weight transposes in one launch; z selects the job
__global__ void k_transpose_all(const float* __restrict__ Wg1,
                                const float* __restrict__ Wg2,
                                const float* __restrict__ Wp,
                                const float* __restrict__ Wfb,
                                const float* __restrict__ Wf) {
    __shared__ float t[32][33];
    const float* in; float* out; int R, C, gx, gy;
    switch (blockIdx.z) {
        case 0: in = Wg1; out = g_Wg1T; R = D;  C = DIN;   gx = 32; gy = 8; break;
        case 1: in = Wg2; out = g_Wg2T; R = DG; C = D;     gx = 8;  gy = 4; break;
        case 2: in = Wp;  out = g_WpT;  R = DG; C = DG;    gx = 4;  gy = 4; break;
        case 3: in = Wfb; out = g_WfbT; R = D;  C = DB;    gx = 2;  gy = 8; break;
        default: in = Wf; out = g_WfT;  R = D;  C = D+DG;  gx = 12; gy = 8; break;
    }
    if ((int)blockIdx.x >= gx || (int)blockIdx.y >= gy) return;
    int cb = blockIdx.x * 32, rb = blockIdx.y * 32;
    int x = cb + threadIdx.x;
#pragma unroll
    for (int j = 0; j < 32; j += 8) {
        int r = rb + threadIdx.y + j;
        t[threadIdx.y + j][threadIdx.x] = in[(size_t)r * C + x];
    }
    __syncthreads();
    int ox = rb + threadIdx.x;
#pragma unroll
    for (int j = 0; j < 32; j += 8) {
        int c = cb + threadIdx.y + j;
        out[(size_t)c * R + ox] = t[threadIdx.x][threadIdx.y + j];
    }
}

__global__ void k_wc(const float* __restrict__ Wtb, const float* __restrict__ Wl2,
                     const float* __restrict__ bl2, const float* __restrict__ btb) {
    __shared__ float sw[D];
    int i = blockIdx.x, j = threadIdx.x;
    sw[j] = Wtb[i*D + j];
    __syncthreads();
    float acc = 0.f;
#pragma unroll 4
    for (int r = 0; r < D; r++) acc += sw[r] * Wl2[r*D + j];
    g_Wc[i*D + j] = acc;
    if (j == 0) {
        float a = btb[i];
        for (int r = 0; r < D; r++) a += sw[r] * bl2[r];
        g_bc[i] = a;
    }
}

__global__ void k_nck(const float* __restrict__ cb2) {
    __shared__ float sred[4];
    int bk = blockIdx.x, t = threadIdx.x;
    float v = cb2[bk*DB + t];
    float q = v*v;
#pragma unroll
    for (int off = 16; off; off >>= 1) q += __shfl_xor_sync(0xffffffffu, q, off);
    if ((t & 31) == 0) sred[t >> 5] = q;
    __syncthreads();
    float nrm = sqrtf(sred[0] + sred[1]);
    float nv = v / fmaxf(nrm, 1e-12f);
    g_nck[bk*DB + t] = nv;
    float s = nv;
#pragma unroll
    for (int off = 16; off; off >>= 1) s += __shfl_xor_sync(0xffffffffu, s, off);
    if ((t & 31) == 0) sred[2 + (t >> 5)] = s;
    __syncthreads();
    if (t == 0) g_snck[bk] = sred[2] + sred[3];
}

__global__ void k_Md() {
    __shared__ float sN[NL2*65];
    int i = blockIdx.x, tid = threadIdx.x;
    int k = tid & 31, cl = tid >> 5;
    int c = blockIdx.y * 8 + cl;
    for (int t = tid; t < NL2*DB; t += 256) {
        int kk = t / DB, rr = t % DB;
        sN[kk*65 + rr] = g_nck[i*NL2*DB + t];
    }
    __syncthreads();
    float acc = 0.f, cs = 0.f;
#pragma unroll 4
    for (int r = 0; r < DB; r++) {
        float wv = g_Wc[r*D + c];
        acc += wv * sN[k*65 + r];
        cs  += wv;
    }
    float sn = g_snck[i*NL2 + k];
    g_Mall[i*(D*NL2) + c*NL2 + k] = acc - cs * sn * (1.f/DB);
    if (blockIdx.y == 0 && cl == 0) {
        float dv = 0.f, bs = 0.f;
        for (int r = 0; r < DB; r++) {
            float b = g_bc[r];
            dv += b * sN[k*65 + r];
            bs += b;
        }
        g_dall[i*NL2 + k] = dv - bs * (1.f/DB) * sn;
    }
}

__global__ void k_table(const float* __restrict__ cb2, const float* __restrict__ bfb,
                        const float* __restrict__ cb1, const float* __restrict__ bf) {
    __shared__ float se[DB];
    __shared__ float sl[D];
    __shared__ float sc1[DG];
    __shared__ float sred[16];
    int bid = blockIdx.x;
    int i = bid >> 5;
    int j = threadIdx.x;
    if (j < DB) se[j] = cb2[bid*DB + j];
    if (j >= 128) sc1[j - 128] = cb1[i*DG + (j - 128)];
    __syncthreads();
    float a = bfb[j];
#pragma unroll 4
    for (int r = 0; r < DB; r++) a += se[r] * g_WfbT[r*D + j];
    float mean, rinv;
    blockLN256(a, j, sred, mean, rinv);
    sl[j] = (a - mean) * rinv;
    __syncthreads();
    float o = bf[j];
#pragma unroll 4
    for (int r = 0; r < D; r++) o += sl[r] * g_WfT[r*D + j];
#pragma unroll 4
    for (int r = 0; r < DG; r++) o += sc1[r] * g_WfT[(D + r)*D + j];
    blockLN256(o, j, sred, mean, rinv);
    g_table[bid*D + j] = fmaxf((o - mean) * rinv, 0.f);
}

__global__ void k_gs1(const float* __restrict__ x) {
    int bx = blockIdx.x;
    int b = bx >> 4, dc = (bx >> 2) & 3, tc = bx & 3;
    int d = dc * 256 + threadIdx.x;
    const float* p = x + ((size_t)b * TLEN + tc * 512) * DIN + d;
    float s = 0.f, q = 0.f;
    for (int t = 0; t < 512; t++) {
        float v = p[(size_t)t * DIN];
        s += v; q += v * v;
    }
    g_part[(b*4 + tc)*DIN + d] = s;
    g_part[BATCH*4*DIN + (b*4 + tc)*DIN + d] = q;
}

__global__ void k_gs2() {
    int b = blockIdx.x >> 2, dc = blockIdx.x & 3;
    int d = dc * 256 + threadIdx.x;
    float s = 0.f, q = 0.f;
#pragma unroll
    for (int tc = 0; tc < 4; tc++) {
        s += g_part[(b*4 + tc)*DIN + d];
        q += g_part[BATCH*4*DIN + (b*4 + tc)*DIN + d];
    }
    float mean = s * (1.f / TLEN);
    float var = (q - s * s * (1.f / TLEN)) * (1.f / (TLEN - 1));
    g_gin[b*DIN + d] = mean + sqrtf(fmaxf(var, 0.f));
}

__global__ void k_global(const float* __restrict__ bg1, const float* __restrict__ bg2,
                         const float* __restrict__ bp,  const float* __restrict__ cb1) {
    __shared__ float sg[DIN];
    __shared__ float sh[D];
    __shared__ float sgp[DG];
    __shared__ float sz[DG];
    __shared__ float sred[16];
    __shared__ float slog[NL1];
    int b = blockIdx.x, j = threadIdx.x;
    for (int t = j; t < DIN; t += 256) sg[t] = g_gin[b*DIN + t];
    __syncthreads();
    float a = bg1[j];
#pragma unroll 4
    for (int r = 0; r < DIN; r++) a += sg[r] * g_Wg1T[r*D + j];
    float mean, rinv;
    blockLN256(a, j, sred, mean, rinv);
    sh[j] = fmaxf((a - mean) * rinv, 0.f);
    __syncthreads();
    if (j < DG) {
        float g2 = bg2[j];
#pragma unroll 4
        for (int r = 0; r < D; r++) g2 += sh[r] * g_Wg2T[r*DG + j];
        sgp[j] = g2;
    }
    __syncthreads();
    if (j < DG) {
        float z = bp[j];
#pragma unroll 4
        for (int r = 0; r < DG; r++) z += sgp[r] * g_WpT[r*DG + j];
        sz[j] = z;
    }
    __syncthreads();
    {
        float zv = (j < DG) ? sz[j] : 0.f;
        float s = zv;
#pragma unroll
        for (int off = 16; off; off >>= 1) s += __shfl_xor_sync(0xffffffffu, s, off);
        if ((j & 31) == 0) sred[j >> 5] = s;
        __syncthreads();
    }
    float meanz = (sred[0]+sred[1]+sred[2]+sred[3]+sred[4]+sred[5]+sred[6]+sred[7]) * (1.f/DG);
    if (j < NL1) {
        float dz = 0.f, cs = 0.f, nn = 0.f;
        const float* cr = cb1 + j*DG;
        for (int r = 0; r < DG; r++) {
            float cv = cr[r];
            dz += sz[r]*cv; cs += cv; nn += cv*cv;
        }
        slog[j] = (dz - meanz*cs) / fmaxf(sqrtf(nn), 1e-12f);
    }
    __syncthreads();
    if (j == 0) {
        float best = slog[0]; int bi = 0;
        for (int t = 1; t < NL1; t++) if (slog[t] > best) { best = slog[t]; bi = t; }
        g_idx1[b] = bi;
    }
}

// -------- fp32 FFMA SGEMM (R2-proven): u = x @ Wl1.T + bl1 --------
// M=32768, N=256, K=1024; 128x128x16 tiles, 256 thr, 8x8/thread
__global__ __launch_bounds__(256, 2)
void k_sgemm(const float* __restrict__ A, const float* __restrict__ Bm,
             const float* __restrict__ bias) {
    __shared__ float As[2][16][128];
    __shared__ float Bs[2][16][128];
    const int K = DIN;
    int tid = threadIdx.x;
    int lr = tid >> 2;
    int lk = (tid & 3) << 2;
    const float* Ap = A  + (size_t)(blockIdx.y * 128) * K;
    const float* Bp = Bm + (size_t)(blockIdx.x * 128) * K;
    int tx = tid & 15, ty = tid >> 4;
    int ar0 = ty * 4, ar1 = 64 + ty * 4;
    int bc0 = tx * 4, bc1 = 64 + tx * 4;
    float acc[8][8];
#pragma unroll
    for (int i = 0; i < 8; i++)
#pragma unroll
        for (int jj = 0; jj < 8; jj++) acc[i][jj] = 0.f;

    float4 ra0, ra1, rb0, rb1;
    ra0 = *(const float4*)(Ap + (size_t)lr * K + lk);
    ra1 = *(const float4*)(Ap + (size_t)(lr + 64) * K + lk);
    rb0 = *(const float4*)(Bp + (size_t)lr * K + lk);
    rb1 = *(const float4*)(Bp + (size_t)(lr + 64) * K + lk);
    As[0][lk+0][lr]    = ra0.x; As[0][lk+1][lr]    = ra0.y; As[0][lk+2][lr]    = ra0.z; As[0][lk+3][lr]    = ra0.w;
    As[0][lk+0][lr+64] = ra1.x; As[0][lk+1][lr+64] = ra1.y; As[0][lk+2][lr+64] = ra1.z; As[0][lk+3][lr+64] = ra1.w;
    Bs[0][lk+0][lr]    = rb0.x; Bs[0][lk+1][lr]    = rb0.y; Bs[0][lk+2][lr]    = rb0.z; Bs[0][lk+3][lr]    = rb0.w;
    Bs[0][lk+0][lr+64] = rb1.x; Bs[0][lk+1][lr+64] = rb1.y; Bs[0][lk+2][lr+64] = rb1.z; Bs[0][lk+3][lr+64] = rb1.w;
    __syncthreads();

    for (int kt = 0; kt < 64; kt++) {
        int cur = kt & 1;
        if (kt < 63) {
            const float* Ak = Ap + (kt + 1) * 16 + lk;
            const float* Bk = Bp + (kt + 1) * 16 + lk;
            ra0 = *(const float4*)(Ak + (size_t)lr * K);
            ra1 = *(const float4*)(Ak + (size_t)(lr + 64) * K);
            rb0 = *(const float4*)(Bk + (size_t)lr * K);
            rb1 = *(const float4*)(Bk + (size_t)(lr + 64) * K);
        }
#pragma unroll
        for (int kk = 0; kk < 16; kk++) {
            float4 fa0 = *(const float4*)&As[cur][kk][ar0];
            float4 fa1 = *(const float4*)&As[cur][kk][ar1];
            float4 fb0 = *(const float4*)&Bs[cur][kk][bc0];
            float4 fb1 = *(const float4*)&Bs[cur][kk][bc1];
            float av[8] = {fa0.x, fa0.y, fa0.z, fa0.w, fa1.x, fa1.y, fa1.z, fa1.w};
            float bv[8] = {fb0.x, fb0.y, fb0.z, fb0.w, fb1.x, fb1.y, fb1.z, fb1.w};
#pragma unroll
            for (int i = 0; i < 8; i++)
#pragma unroll
                for (int jj = 0; jj < 8; jj++) acc[i][jj] += av[i] * bv[jj];
        }
        if (kt < 63) {
            int nxt = cur ^ 1;
            As[nxt][lk+0][lr]    = ra0.x; As[nxt][lk+1][lr]    = ra0.y; As[nxt][lk+2][lr]    = ra0.z; As[nxt][lk+3][lr]    = ra0.w;
            As[nxt][lk+0][lr+64] = ra1.x; As[nxt][lk+1][lr+64] = ra1.y; As[nxt][lk+2][lr+64] = ra1.z; As[nxt][lk+3][lr+64] = ra1.w;
            Bs[nxt][lk+0][lr]    = rb0.x; Bs[nxt][lk+1][lr]    = rb0.y; Bs[nxt][lk+2][lr]    = rb0.z; Bs[nxt][lk+3][lr]    = rb0.w;
            Bs[nxt][lk+0][lr+64] = rb1.x; Bs[nxt][lk+1][lr+64] = rb1.y; Bs[nxt][lk+2][lr+64] = rb1.z; Bs[nxt][lk+3][lr+64] = rb1.w;
            __syncthreads();
        }
    }
    int row0 = blockIdx.y * 128;
    int col0 = blockIdx.x * 128;
    float4 bA = *(const float4*)(bias + col0 + bc0);
    float4 bB = *(const float4*)(bias + col0 + bc1);
#pragma unroll
    for (int i = 0; i < 8; i++) {
        int r = row0 + ((i < 4) ? (ar0 + i) : (ar1 + i - 4));
        float4 v0 = make_float4(acc[i][0] + bA.x, acc[i][1] + bA.y,
                                acc[i][2] + bA.z, acc[i][3] + bA.w);
        float4 v1 = make_float4(acc[i][4] + bB.x, acc[i][5] + bB.y,
                                acc[i][6] + bB.z, acc[i][7] + bB.w);
        *(float4*)(g_U + (size_t)r * D + col0 + bc0) = v0;
        *(float4*)(g_U + (size_t)r * D + col0 + bc1) = v1;
    }
}

__global__ __launch_bounds__(256)
void k_epilogue(float* __restrict__ out) {
    __shared__ float sM[D * NL2];
    __shared__ float sd[NL2];
    __shared__ int si1;
    int b = blockIdx.x;
    int tid = threadIdx.x;
    int lane = tid & 31;
    int w = tid >> 5;
    if (tid == 0) si1 = g_idx1[b];
    __syncthreads();
    int i1 = si1;
    {
        const float4* src = (const float4*)(g_Mall + (size_t)i1 * D * NL2);
        float4* dst = (float4*)sM;
        for (int t = tid; t < D * NL2 / 4; t += 256) dst[t] = src[t];
        if (tid < NL2) sd[tid] = g_dall[i1 * NL2 + tid];
    }
    __syncthreads();
    int rowBase = b * TLEN + blockIdx.y * 128 + w * 16;
    for (int r = 0; r < 16; r++) {
        int row = rowBase + r;
        const float4* up = (const float4*)(g_U + (size_t)row * D);
        float4 u0 = up[lane];
        float4 u1 = up[lane + 32];
        float h[8] = {u0.x, u0.y, u0.z, u0.w, u1.x, u1.y, u1.z, u1.w};
        float s = 0.f, q = 0.f;
#pragma unroll
        for (int e = 0; e < 8; e++) { s += h[e]; q += h[e]*h[e]; }
#pragma unroll
        for (int off = 16; off; off >>= 1) {
            s += __shfl_xor_sync(0xffffffffu, s, off);
            q += __shfl_xor_sync(0xffffffffu, q, off);
        }
        float mean = s * (1.f / 256.f);
        float var = q * (1.f / 256.f) - mean * mean;
        float rinv = rsqrtf(fmaxf(var, 0.f) + 1e-5f);
#pragma unroll
        for (int e = 0; e < 8; e++) h[e] = fmaxf((h[e] - mean) * rinv, 0.f);
        float acc = sd[lane];
#pragma unroll
        for (int e = 0; e < 8; e++) {
            int cb = (e < 4) ? e : (e + 124);
#pragma unroll 8
            for (int srcl = 0; srcl < 32; srcl++) {
                float hv = __shfl_sync(0xffffffffu, h[e], srcl);
                acc += hv * sM[(srcl * 4 + cb) * NL2 + lane];
            }
        }
        float best = acc; int bidx = lane;
#pragma unroll
        for (int off = 16; off; off >>= 1) {
            float ov = __shfl_xor_sync(0xffffffffu, best, off);
            int   oi = __shfl_xor_sync(0xffffffffu, bidx, off);
            if (ov > best || (ov == best && oi < bidx)) { best = ov; bidx = oi; }
        }
        const float4* trow = (const float4*)(g_table + (size_t)(i1 * NL2 + bidx) * D);
        float4* orow = (float4*)(out + (size_t)row * D);
        orow[lane]      = trow[lane];
        orow[lane + 32] = trow[lane + 32];
    }
}

extern "C" void kernel_launch(void* const* d_in, const int* in_sizes, int n_in,
                              void* d_out, int out_size) {
    const float* x   = (const float*)d_in[0];
    const float* Wg1 = (const float*)d_in[1];
    const float* bg1 = (const float*)d_in[2];
    const float* Wg2 = (const float*)d_in[3];
    const float* bg2 = (const float*)d_in[4];
    const float* Wl1 = (const float*)d_in[5];
    const float* bl1 = (const float*)d_in[6];
    const float* Wl2 = (const float*)d_in[7];
    const float* bl2 = (const float*)d_in[8];
    const float* Wp  = (const float*)d_in[9];
    const float* bp  = (const float*)d_in[10];
    const float* cb1 = (const float*)d_in[11];
    const float* Wtb = (const float*)d_in[12];
    const float* btb = (const float*)d_in[13];
    const float* Wfb = (const float*)d_in[14];
    const float* bfb = (const float*)d_in[15];
    const float* cb2 = (const float*)d_in[16];
    const float* Wf  = (const float*)d_in[17];
    const float* bf  = (const float*)d_in[18];
    float* out = (float*)d_out;

    dim3 tb(32, 8);
    k_transpose_all<<<dim3(32, 8, 5), tb>>>(Wg1, Wg2, Wp, Wfb, Wf);
    k_wc   <<<64, 256>>>(Wtb, Wl2, bl2, btb);
    k_nck  <<<256, 64>>>(cb2);
    k_Md   <<<dim3(8, 32), 256>>>();
    k_table<<<256, 256>>>(cb2, bfb, cb1, bf);
    k_gs1  <<<256, 256>>>(x);
    k_gs2  <<<64, 256>>>();
    k_global<<<16, 256>>>(bg1, bg2, bp, cb1);
    k_sgemm<<<dim3(2, 256), 256>>>(x, Wl1, bl1);
    k_epilogue<<<dim3(16, 16), 256>>>(out);
}

// round 16
// speedup vs baseline: 1.6622x; 1.0003x over previous
#include <cuda_runtime.h>
#include <cuda_bf16.h>
#include <math.h>

typedef unsigned long long u64;

#define DIN 1024
#define D   256
#define DG  128
#define DB  64
#define NL1 8
#define NL2 32
#define BATCH 16
#define TLEN 2048
#define MROWS (BATCH*TLEN)

__device__ float g_U[MROWS*D];
__device__ float g_gin[BATCH*DIN];
__device__ int   g_idx1[BATCH];
__device__ float g_Wc[DB*D];
__device__ float g_bc[DB];
__device__ float g_nck[NL1*NL2*DB];
__device__ float g_snck[NL1*NL2];
__device__ float g_Mall[NL1*D*NL2];
__device__ float g_dall[NL1*NL2];
__device__ float g_table[NL1*NL2*D];
__device__ float g_Wg1T[DIN*D];
__device__ float g_Wg2T[D*DG];
__device__ float g_WpT[DG*DG];
__device__ float g_WfbT[DB*D];
__device__ float g_WfT[(D+DG)*D];
__device__ float g_part[2*BATCH*4*DIN];

__device__ __forceinline__ void blockLN256(float v, int tid, float* sred,
                                           float& mean, float& rinv) {
    __syncthreads();
    float s = v, q = v*v;
#pragma unroll
    for (int off = 16; off; off >>= 1) {
        s += __shfl_xor_sync(0xffffffffu, s, off);
        q += __shfl_xor_sync(0xffffffffu, q, off);
    }
    if ((tid & 31) == 0) { sred[tid >> 5] = s; sred[8 + (tid >> 5)] = q; }
    __syncthreads();
    float ts = 0.f, tq = 0.f;
#pragma unroll
    for (int w = 0; w < 8; w++) { ts += sred[w]; tq += sred[8 + w]; }
    mean = ts * (1.f / 256.f);
    float var = tq * (1.f / 256.f) - mean * mean;
    rinv = rsqrtf(fmaxf(var, 0.f) + 1e-5f);
}

// all 5 weight transposes in one launch; z selects the job
__global__ void k_transpose_all(const float* __restrict__ Wg1,
                                const float* __restrict__ Wg2,
                                const float* __restrict__ Wp,
                                const float* __restrict__ Wfb,
                                const float* __restrict__ Wf) {
    __shared__ float t[32][33];
    const float* in; float* out; int R, C, gx, gy;
    switch (blockIdx.z) {
        case 0: in = Wg1; out = g_Wg1T; R = D;  C = DIN;   gx = 32; gy = 8; break;
        case 1: in = Wg2; out = g_Wg2T; R = DG; C = D;     gx = 8;  gy = 4; break;
        case 2: in = Wp;  out = g_WpT;  R = DG; C = DG;    gx = 4;  gy = 4; break;
        case 3: in = Wfb; out = g_WfbT; R = D;  C = DB;    gx = 2;  gy = 8; break;
        default: in = Wf; out = g_WfT;  R = D;  C = D+DG;  gx = 12; gy = 8; break;
    }
    if ((int)blockIdx.x >= gx || (int)blockIdx.y >= gy) return;
    int cb = blockIdx.x * 32, rb = blockIdx.y * 32;
    int x = cb + threadIdx.x;
#pragma unroll
    for (int j = 0; j < 32; j += 8) {
        int r = rb + threadIdx.y + j;
        t[threadIdx.y + j][threadIdx.x] = in[(size_t)r * C + x];
    }
    __syncthreads();
    int ox = rb + threadIdx.x;
#pragma unroll
    for (int j = 0; j < 32; j += 8) {
        int c = cb + threadIdx.y + j;
        out[(size_t)c * R + ox] = t[threadIdx.x][threadIdx.y + j];
    }
}

__global__ void k_wc(const float* __restrict__ Wtb, const float* __restrict__ Wl2,
                     const float* __restrict__ bl2, const float* __restrict__ btb) {
    __shared__ float sw[D];
    int i = blockIdx.x, j = threadIdx.x;
    sw[j] = Wtb[i*D + j];
    __syncthreads();
    float acc = 0.f;
#pragma unroll 4
    for (int r = 0; r < D; r++) acc += sw[r] * Wl2[r*D + j];
    g_Wc[i*D + j] = acc;
    if (j == 0) {
        float a = btb[i];
        for (int r = 0; r < D; r++) a += sw[r] * bl2[r];
        g_bc[i] = a;
    }
}

__global__ void k_nck(const float* __restrict__ cb2) {
    __shared__ float sred[4];
    int bk = blockIdx.x, t = threadIdx.x;
    float v = cb2[bk*DB + t];
    float q = v*v;
#pragma unroll
    for (int off = 16; off; off >>= 1) q += __shfl_xor_sync(0xffffffffu, q, off);
    if ((t & 31) == 0) sred[t >> 5] = q;
    __syncthreads();
    float nrm = sqrtf(sred[0] + sred[1]);
    float nv = v / fmaxf(nrm, 1e-12f);
    g_nck[bk*DB + t] = nv;
    float s = nv;
#pragma unroll
    for (int off = 16; off; off >>= 1) s += __shfl_xor_sync(0xffffffffu, s, off);
    if ((t & 31) == 0) sred[2 + (t >> 5)] = s;
    __syncthreads();
    if (t == 0) g_snck[bk] = sred[2] + sred[3];
}

__global__ void k_Md() {
    __shared__ float sN[NL2*65];
    int i = blockIdx.x, tid = threadIdx.x;
    int k = tid & 31, cl = tid >> 5;
    int c = blockIdx.y * 8 + cl;
    for (int t = tid; t < NL2*DB; t += 256) {
        int kk = t / DB, rr = t % DB;
        sN[kk*65 + rr] = g_nck[i*NL2*DB + t];
    }
    __syncthreads();
    float acc = 0.f, cs = 0.f;
#pragma unroll 4
    for (int r = 0; r < DB; r++) {
        float wv = g_Wc[r*D + c];
        acc += wv * sN[k*65 + r];
        cs  += wv;
    }
    float sn = g_snck[i*NL2 + k];
    g_Mall[i*(D*NL2) + c*NL2 + k] = acc - cs * sn * (1.f/DB);
    if (blockIdx.y == 0 && cl == 0) {
        float dv = 0.f, bs = 0.f;
        for (int r = 0; r < DB; r++) {
            float b = g_bc[r];
            dv += b * sN[k*65 + r];
            bs += b;
        }
        g_dall[i*NL2 + k] = dv - bs * (1.f/DB) * sn;
    }
}

__global__ void k_table(const float* __restrict__ cb2, const float* __restrict__ bfb,
                        const float* __restrict__ cb1, const float* __restrict__ bf) {
    __shared__ float se[DB];
    __shared__ float sl[D];
    __shared__ float sc1[DG];
    __shared__ float sred[16];
    int bid = blockIdx.x;
    int i = bid >> 5;
    int j = threadIdx.x;
    if (j < DB) se[j] = cb2[bid*DB + j];
    if (j >= 128) sc1[j - 128] = cb1[i*DG + (j - 128)];
    __syncthreads();
    float a = bfb[j];
#pragma unroll 4
    for (int r = 0; r < DB; r++) a += se[r] * g_WfbT[r*D + j];
    float mean, rinv;
    blockLN256(a, j, sred, mean, rinv);
    sl[j] = (a - mean) * rinv;
    __syncthreads();
    float o = bf[j];
#pragma unroll 4
    for (int r = 0; r < D; r++) o += sl[r] * g_WfT[r*D + j];
#pragma unroll 4
    for (int r = 0; r < DG; r++) o += sc1[r] * g_WfT[(D + r)*D + j];
    blockLN256(o, j, sred, mean, rinv);
    g_table[bid*D + j] = fmaxf((o - mean) * rinv, 0.f);
}

__global__ void k_gs1(const float* __restrict__ x) {
    int bx = blockIdx.x;
    int b = bx >> 4, dc = (bx >> 2) & 3, tc = bx & 3;
    int d = dc * 256 + threadIdx.x;
    const float* p = x + ((size_t)b * TLEN + tc * 512) * DIN + d;
    float s = 0.f, q = 0.f;
    for (int t = 0; t < 512; t++) {
        float v = p[(size_t)t * DIN];
        s += v; q += v * v;
    }
    g_part[(b*4 + tc)*DIN + d] = s;
    g_part[BATCH*4*DIN + (b*4 + tc)*DIN + d] = q;
}

__global__ void k_gs2() {
    int b = blockIdx.x >> 2, dc = blockIdx.x & 3;
    int d = dc * 256 + threadIdx.x;
    float s = 0.f, q = 0.f;
#pragma unroll
    for (int tc = 0; tc < 4; tc++) {
        s += g_part[(b*4 + tc)*DIN + d];
        q += g_part[BATCH*4*DIN + (b*4 + tc)*DIN + d];
    }
    float mean = s * (1.f / TLEN);
    float var = (q - s * s * (1.f / TLEN)) * (1.f / (TLEN - 1));
    g_gin[b*DIN + d] = mean + sqrtf(fmaxf(var, 0.f));
}

__global__ void k_global(const float* __restrict__ bg1, const float* __restrict__ bg2,
                         const float* __restrict__ bp,  const float* __restrict__ cb1) {
    __shared__ float sg[DIN];
    __shared__ float sh[D];
    __shared__ float sgp[DG];
    __shared__ float sz[DG];
    __shared__ float sred[16];
    __shared__ float slog[NL1];
    int b = blockIdx.x, j = threadIdx.x;
    for (int t = j; t < DIN; t += 256) sg[t] = g_gin[b*DIN + t];
    __syncthreads();
    float a = bg1[j];
#pragma unroll 4
    for (int r = 0; r < DIN; r++) a += sg[r] * g_Wg1T[r*D + j];
    float mean, rinv;
    blockLN256(a, j, sred, mean, rinv);
    sh[j] = fmaxf((a - mean) * rinv, 0.f);
    __syncthreads();
    if (j < DG) {
        float g2 = bg2[j];
#pragma unroll 4
        for (int r = 0; r < D; r++) g2 += sh[r] * g_Wg2T[r*DG + j];
        sgp[j] = g2;
    }
    __syncthreads();
    if (j < DG) {
        float z = bp[j];
#pragma unroll 4
        for (int r = 0; r < DG; r++) z += sgp[r] * g_WpT[r*DG + j];
        sz[j] = z;
    }
    __syncthreads();
    {
        float zv = (j < DG) ? sz[j] : 0.f;
        float s = zv;
#pragma unroll
        for (int off = 16; off; off >>= 1) s += __shfl_xor_sync(0xffffffffu, s, off);
        if ((j & 31) == 0) sred[j >> 5] = s;
        __syncthreads();
    }
    float meanz = (sred[0]+sred[1]+sred[2]+sred[3]+sred[4]+sred[5]+sred[6]+sred[7]) * (1.f/DG);
    if (j < NL1) {
        float dz = 0.f, cs = 0.f, nn = 0.f;
        const float* cr = cb1 + j*DG;
        for (int r = 0; r < DG; r++) {
            float cv = cr[r];
            dz += sz[r]*cv; cs += cv; nn += cv*cv;
        }
        slog[j] = (dz - meanz*cs) / fmaxf(sqrtf(nn), 1e-12f);
    }
    __syncthreads();
    if (j == 0) {
        float best = slog[0]; int bi = 0;
        for (int t = 1; t < NL1; t++) if (slog[t] > best) { best = slog[t]; bi = t; }
        g_idx1[b] = bi;
    }
}

// -------- fp32 FFMA SGEMM: u = x @ Wl1.T + bl1 --------
// M=32768, N=256, K=1024; 128x64 tiles, 256 thr, 8x4/thread, occ 3
__global__ __launch_bounds__(256, 3)
void k_sgemm(const float* __restrict__ A, const float* __restrict__ Bm,
             const float* __restrict__ bias) {
    __shared__ float As[2][16][128];
    __shared__ float Bs[2][16][64];
    const int K = DIN;
    int tid = threadIdx.x;
    int alr = tid >> 1, alk = (tid & 1) << 3;   // A: row 0..127, col base 0/8
    int blr = tid >> 2, blk = (tid & 3) << 2;   // B: row 0..63, col base 0/4/8/12
    const float* Ap = A  + (size_t)(blockIdx.y * 128 + alr) * K + alk;
    const float* Bp = Bm + (size_t)(blockIdx.x * 64 + blr) * K + blk;
    int tx = tid & 15, ty = tid >> 4;
    int ar0 = ty * 4, ar1 = 64 + ty * 4;
    int bc0 = tx * 4;
    float acc[8][4];
#pragma unroll
    for (int i = 0; i < 8; i++)
#pragma unroll
        for (int jj = 0; jj < 4; jj++) acc[i][jj] = 0.f;

    float4 ra0, ra1, rb0;
    ra0 = *(const float4*)(Ap);
    ra1 = *(const float4*)(Ap + 4);
    rb0 = *(const float4*)(Bp);
    As[0][alk+0][alr] = ra0.x; As[0][alk+1][alr] = ra0.y;
    As[0][alk+2][alr] = ra0.z; As[0][alk+3][alr] = ra0.w;
    As[0][alk+4][alr] = ra1.x; As[0][alk+5][alr] = ra1.y;
    As[0][alk+6][alr] = ra1.z; As[0][alk+7][alr] = ra1.w;
    Bs[0][blk+0][blr] = rb0.x; Bs[0][blk+1][blr] = rb0.y;
    Bs[0][blk+2][blr] = rb0.z; Bs[0][blk+3][blr] = rb0.w;
    __syncthreads();

    for (int kt = 0; kt < 64; kt++) {
        int cur = kt & 1;
        if (kt < 63) {
            int ko = (kt + 1) * 16;
            ra0 = *(const float4*)(Ap + ko);
            ra1 = *(const float4*)(Ap + ko + 4);
            rb0 = *(const float4*)(Bp + ko);
        }
#pragma unroll
        for (int kk = 0; kk < 16; kk++) {
            float4 fa0 = *(const float4*)&As[cur][kk][ar0];
            float4 fa1 = *(const float4*)&As[cur][kk][ar1];
            float4 fb0 = *(const float4*)&Bs[cur][kk][bc0];
            float av[8] = {fa0.x, fa0.y, fa0.z, fa0.w, fa1.x, fa1.y, fa1.z, fa1.w};
            float bv[4] = {fb0.x, fb0.y, fb0.z, fb0.w};
#pragma unroll
            for (int i = 0; i < 8; i++)
#pragma unroll
                for (int jj = 0; jj < 4; jj++) acc[i][jj] += av[i] * bv[jj];
        }
        if (kt < 63) {
            int nxt = cur ^ 1;
            As[nxt][alk+0][alr] = ra0.x; As[nxt][alk+1][alr] = ra0.y;
            As[nxt][alk+2][alr] = ra0.z; As[nxt][alk+3][alr] = ra0.w;
            As[nxt][alk+4][alr] = ra1.x; As[nxt][alk+5][alr] = ra1.y;
            As[nxt][alk+6][alr] = ra1.z; As[nxt][alk+7][alr] = ra1.w;
            Bs[nxt][blk+0][blr] = rb0.x; Bs[nxt][blk+1][blr] = rb0.y;
            Bs[nxt][blk+2][blr] = rb0.z; Bs[nxt][blk+3][blr] = rb0.w;
            __syncthreads();
        }
    }
    int row0 = blockIdx.y * 128;
    int col0 = blockIdx.x * 64 + bc0;
    float4 bA = *(const float4*)(bias + col0);
#pragma unroll
    for (int i = 0; i < 8; i++) {
        int r = row0 + ((i < 4) ? (ar0 + i) : (ar1 + i - 4));
        float4 v0 = make_float4(acc[i][0] + bA.x, acc[i][1] + bA.y,
                                acc[i][2] + bA.z, acc[i][3] + bA.w);
        *(float4*)(g_U + (size_t)r * D + col0) = v0;
    }
}

__global__ __launch_bounds__(256)
void k_epilogue(float* __restrict__ out) {
    __shared__ float sM[D * NL2];
    __shared__ float sd[NL2];
    __shared__ int si1;
    int b = blockIdx.x;
    int tid = threadIdx.x;
    int lane = tid & 31;
    int w = tid >> 5;
    if (tid == 0) si1 = g_idx1[b];
    __syncthreads();
    int i1 = si1;
    {
        const float4* src = (const float4*)(g_Mall + (size_t)i1 * D * NL2);
        float4* dst = (float4*)sM;
        for (int t = tid; t < D * NL2 / 4; t += 256) dst[t] = src[t];
        if (tid < NL2) sd[tid] = g_dall[i1 * NL2 + tid];
    }
    __syncthreads();
    int rowBase = b * TLEN + blockIdx.y * 128 + w * 16;
    for (int r = 0; r < 16; r++) {
        int row = rowBase + r;
        const float4* up = (const float4*)(g_U + (size_t)row * D);
        float4 u0 = up[lane];
        float4 u1 = up[lane + 32];
        float h[8] = {u0.x, u0.y, u0.z, u0.w, u1.x, u1.y, u1.z, u1.w};
        float s = 0.f, q = 0.f;
#pragma unroll
        for (int e = 0; e < 8; e++) { s += h[e]; q += h[e]*h[e]; }
#pragma unroll
        for (int off = 16; off; off >>= 1) {
            s += __shfl_xor_sync(0xffffffffu, s, off);
            q += __shfl_xor_sync(0xffffffffu, q, off);
        }
        float mean = s * (1.f / 256.f);
        float var = q * (1.f / 256.f) - mean * mean;
        float rinv = rsqrtf(fmaxf(var, 0.f) + 1e-5f);
#pragma unroll
        for (int e = 0; e < 8; e++) h[e] = fmaxf((h[e] - mean) * rinv, 0.f);
        float acc = sd[lane];
#pragma unroll
        for (int e = 0; e < 8; e++) {
            int cb = (e < 4) ? e : (e + 124);
#pragma unroll 8
            for (int srcl = 0; srcl < 32; srcl++) {
                float hv = __shfl_sync(0xffffffffu, h[e], srcl);
                acc += hv * sM[(srcl * 4 + cb) * NL2 + lane];
            }
        }
        float best = acc; int bidx = lane;
#pragma unroll
        for (int off = 16; off; off >>= 1) {
            float ov = __shfl_xor_sync(0xffffffffu, best, off);
            int   oi = __shfl_xor_sync(0xffffffffu, bidx, off);
            if (ov > best || (ov == best && oi < bidx)) { best = ov; bidx = oi; }
        }
        const float4* trow = (const float4*)(g_table + (size_t)(i1 * NL2 + bidx) * D);
        float4* orow = (float4*)(out + (size_t)row * D);
        orow[lane]      = trow[lane];
        orow[lane + 32] = trow[lane + 32];
    }
}

extern "C" void kernel_launch(void* const* d_in, const int* in_sizes, int n_in,
                              void* d_out, int out_size) {
    const float* x   = (const float*)d_in[0];
    const float* Wg1 = (const float*)d_in[1];
    const float* bg1 = (const float*)d_in[2];
    const float* Wg2 = (const float*)d_in[3];
    const float* bg2 = (const float*)d_in[4];
    const float* Wl1 = (const float*)d_in[5];
    const float* bl1 = (const float*)d_in[6];
    const float* Wl2 = (const float*)d_in[7];
    const float* bl2 = (const float*)d_in[8];
    const float* Wp  = (const float*)d_in[9];
    const float* bp  = (const float*)d_in[10];
    const float* cb1 = (const float*)d_in[11];
    const float* Wtb = (const float*)d_in[12];
    const float* btb = (const float*)d_in[13];
    const float* Wfb = (const float*)d_in[14];
    const float* bfb = (const float*)d_in[15];
    const float* cb2 = (const float*)d_in[16];
    const float* Wf  = (const float*)d_in[17];
    const float* bf  = (const float*)d_in[18];
    float* out = (float*)d_out;

    dim3 tb(32, 8);
    k_transpose_all<<<dim3(32, 8, 5), tb>>>(Wg1, Wg2, Wp, Wfb, Wf);
    k_wc   <<<64, 256>>>(Wtb, Wl2, bl2, btb);
    k_nck  <<<256, 64>>>(cb2);
    k_Md   <<<dim3(8, 32), 256>>>();
    k_table<<<256, 256>>>(cb2, bfb, cb1, bf);
    k_gs1  <<<256, 256>>>(x);
    k_gs2  <<<64, 256>>>();
    k_global<<<16, 256>>>(bg1, bg2, bp, cb1);
    k_sgemm<<<dim3(4, 256), 256>>>(x, Wl1, bl1);
    k_epilogue<<<dim3(16, 16), 256>>>(out);
}

// round 17
// speedup vs baseline: 1.8514x; 1.1138x over previous
#include <cuda_runtime.h>
#include <cuda_bf16.h>
#include <math.h>

typedef unsigned long long u64;

#define DIN 1024
#define D   256
#define DG  128
#define DB  64
#define NL1 8
#define NL2 32
#define BATCH 16
#define TLEN 2048
#define MROWS (BATCH*TLEN)

__device__ float g_U[MROWS*D];
__device__ float g_gin[BATCH*DIN];
__device__ int   g_idx1[BATCH];
__device__ float g_Wc[DB*D];
__device__ float g_bc[DB];
__device__ float g_nck[NL1*NL2*DB];
__device__ float g_snck[NL1*NL2];
__device__ float g_Mall[NL1*D*NL2];
__device__ float g_dall[NL1*NL2];
__device__ float g_table[NL1*NL2*D];
__device__ float g_Wg1T[DIN*D];
__device__ float g_Wg2T[D*DG];
__device__ float g_WpT[DG*DG];
__device__ float g_WfbT[DB*D];
__device__ float g_WfT[(D+DG)*D];
__device__ float g_part[2*BATCH*4*DIN];

__device__ __forceinline__ void blockLN256(float v, int tid, float* sred,
                                           float& mean, float& rinv) {
    __syncthreads();
    float s = v, q = v*v;
#pragma unroll
    for (int off = 16; off; off >>= 1) {
        s += __shfl_xor_sync(0xffffffffu, s, off);
        q += __shfl_xor_sync(0xffffffffu, q, off);
    }
    if ((tid & 31) == 0) { sred[tid >> 5] = s; sred[8 + (tid >> 5)] = q; }
    __syncthreads();
    float ts = 0.f, tq = 0.f;
#pragma unroll
    for (int w = 0; w < 8; w++) { ts += sred[w]; tq += sred[8 + w]; }
    mean = ts * (1.f / 256.f);
    float var = tq * (1.f / 256.f) - mean * mean;
    rinv = rsqrtf(fmaxf(var, 0.f) + 1e-5f);
}

// all 5 weight transposes in one launch; z selects the job
__global__ void k_transpose_all(const float* __restrict__ Wg1,
                                const float* __restrict__ Wg2,
                                const float* __restrict__ Wp,
                                const float* __restrict__ Wfb,
                                const float* __restrict__ Wf) {
    __shared__ float t[32][33];
    const float* in; float* out; int R, C, gx, gy;
    switch (blockIdx.z) {
        case 0: in = Wg1; out = g_Wg1T; R = D;  C = DIN;   gx = 32; gy = 8; break;
        case 1: in = Wg2; out = g_Wg2T; R = DG; C = D;     gx = 8;  gy = 4; break;
        case 2: in = Wp;  out = g_WpT;  R = DG; C = DG;    gx = 4;  gy = 4; break;
        case 3: in = Wfb; out = g_WfbT; R = D;  C = DB;    gx = 2;  gy = 8; break;
        default: in = Wf; out = g_WfT;  R = D;  C = D+DG;  gx = 12; gy = 8; break;
    }
    if ((int)blockIdx.x >= gx || (int)blockIdx.y >= gy) return;
    int cb = blockIdx.x * 32, rb = blockIdx.y * 32;
    int x = cb + threadIdx.x;
#pragma unroll
    for (int j = 0; j < 32; j += 8) {
        int r = rb + threadIdx.y + j;
        t[threadIdx.y + j][threadIdx.x] = in[(size_t)r * C + x];
    }
    __syncthreads();
    int ox = rb + threadIdx.x;
#pragma unroll
    for (int j = 0; j < 32; j += 8) {
        int c = cb + threadIdx.y + j;
        out[(size_t)c * R + ox] = t[threadIdx.x][threadIdx.y + j];
    }
}

__global__ void k_wc(const float* __restrict__ Wtb, const float* __restrict__ Wl2,
                     const float* __restrict__ bl2, const float* __restrict__ btb) {
    __shared__ float sw[D];
    int i = blockIdx.x, j = threadIdx.x;
    sw[j] = Wtb[i*D + j];
    __syncthreads();
    float acc = 0.f;
#pragma unroll 4
    for (int r = 0; r < D; r++) acc += sw[r] * Wl2[r*D + j];
    g_Wc[i*D + j] = acc;
    if (j == 0) {
        float a = btb[i];
        for (int r = 0; r < D; r++) a += sw[r] * bl2[r];
        g_bc[i] = a;
    }
}

__global__ void k_nck(const float* __restrict__ cb2) {
    __shared__ float sred[4];
    int bk = blockIdx.x, t = threadIdx.x;
    float v = cb2[bk*DB + t];
    float q = v*v;
#pragma unroll
    for (int off = 16; off; off >>= 1) q += __shfl_xor_sync(0xffffffffu, q, off);
    if ((t & 31) == 0) sred[t >> 5] = q;
    __syncthreads();
    float nrm = sqrtf(sred[0] + sred[1]);
    float nv = v / fmaxf(nrm, 1e-12f);
    g_nck[bk*DB + t] = nv;
    float s = nv;
#pragma unroll
    for (int off = 16; off; off >>= 1) s += __shfl_xor_sync(0xffffffffu, s, off);
    if ((t & 31) == 0) sred[2 + (t >> 5)] = s;
    __syncthreads();
    if (t == 0) g_snck[bk] = sred[2] + sred[3];
}

__global__ void k_Md() {
    __shared__ float sN[NL2*65];
    int i = blockIdx.x, tid = threadIdx.x;
    int k = tid & 31, cl = tid >> 5;
    int c = blockIdx.y * 8 + cl;
    for (int t = tid; t < NL2*DB; t += 256) {
        int kk = t / DB, rr = t % DB;
        sN[kk*65 + rr] = g_nck[i*NL2*DB + t];
    }
    __syncthreads();
    float acc = 0.f, cs = 0.f;
#pragma unroll 4
    for (int r = 0; r < DB; r++) {
        float wv = g_Wc[r*D + c];
        acc += wv * sN[k*65 + r];
        cs  += wv;
    }
    float sn = g_snck[i*NL2 + k];
    g_Mall[i*(D*NL2) + c*NL2 + k] = acc - cs * sn * (1.f/DB);
    if (blockIdx.y == 0 && cl == 0) {
        float dv = 0.f, bs = 0.f;
        for (int r = 0; r < DB; r++) {
            float b = g_bc[r];
            dv += b * sN[k*65 + r];
            bs += b;
        }
        g_dall[i*NL2 + k] = dv - bs * (1.f/DB) * sn;
    }
}

__global__ void k_table(const float* __restrict__ cb2, const float* __restrict__ bfb,
                        const float* __restrict__ cb1, const float* __restrict__ bf) {
    __shared__ float se[DB];
    __shared__ float sl[D];
    __shared__ float sc1[DG];
    __shared__ float sred[16];
    int bid = blockIdx.x;
    int i = bid >> 5;
    int j = threadIdx.x;
    if (j < DB) se[j] = cb2[bid*DB + j];
    if (j >= 128) sc1[j - 128] = cb1[i*DG + (j - 128)];
    __syncthreads();
    float a = bfb[j];
#pragma unroll 4
    for (int r = 0; r < DB; r++) a += se[r] * g_WfbT[r*D + j];
    float mean, rinv;
    blockLN256(a, j, sred, mean, rinv);
    sl[j] = (a - mean) * rinv;
    __syncthreads();
    float o = bf[j];
#pragma unroll 4
    for (int r = 0; r < D; r++) o += sl[r] * g_WfT[r*D + j];
#pragma unroll 4
    for (int r = 0; r < DG; r++) o += sc1[r] * g_WfT[(D + r)*D + j];
    blockLN256(o, j, sred, mean, rinv);
    g_table[bid*D + j] = fmaxf((o - mean) * rinv, 0.f);
}

__global__ void k_gs1(const float* __restrict__ x) {
    int bx = blockIdx.x;
    int b = bx >> 4, dc = (bx >> 2) & 3, tc = bx & 3;
    int d = dc * 256 + threadIdx.x;
    const float* p = x + ((size_t)b * TLEN + tc * 512) * DIN + d;
    float s = 0.f, q = 0.f;
    for (int t = 0; t < 512; t++) {
        float v = p[(size_t)t * DIN];
        s += v; q += v * v;
    }
    g_part[(b*4 + tc)*DIN + d] = s;
    g_part[BATCH*4*DIN + (b*4 + tc)*DIN + d] = q;
}

__global__ void k_gs2() {
    int b = blockIdx.x >> 2, dc = blockIdx.x & 3;
    int d = dc * 256 + threadIdx.x;
    float s = 0.f, q = 0.f;
#pragma unroll
    for (int tc = 0; tc < 4; tc++) {
        s += g_part[(b*4 + tc)*DIN + d];
        q += g_part[BATCH*4*DIN + (b*4 + tc)*DIN + d];
    }
    float mean = s * (1.f / TLEN);
    float var = (q - s * s * (1.f / TLEN)) * (1.f / (TLEN - 1));
    g_gin[b*DIN + d] = mean + sqrtf(fmaxf(var, 0.f));
}

__global__ void k_global(const float* __restrict__ bg1, const float* __restrict__ bg2,
                         const float* __restrict__ bp,  const float* __restrict__ cb1) {
    __shared__ float sg[DIN];
    __shared__ float sh[D];
    __shared__ float sgp[DG];
    __shared__ float sz[DG];
    __shared__ float sred[16];
    __shared__ float slog[NL1];
    int b = blockIdx.x, j = threadIdx.x;
    for (int t = j; t < DIN; t += 256) sg[t] = g_gin[b*DIN + t];
    __syncthreads();
    float a = bg1[j];
#pragma unroll 4
    for (int r = 0; r < DIN; r++) a += sg[r] * g_Wg1T[r*D + j];
    float mean, rinv;
    blockLN256(a, j, sred, mean, rinv);
    sh[j] = fmaxf((a - mean) * rinv, 0.f);
    __syncthreads();
    if (j < DG) {
        float g2 = bg2[j];
#pragma unroll 4
        for (int r = 0; r < D; r++) g2 += sh[r] * g_Wg2T[r*DG + j];
        sgp[j] = g2;
    }
    __syncthreads();
    if (j < DG) {
        float z = bp[j];
#pragma unroll 4
        for (int r = 0; r < DG; r++) z += sgp[r] * g_WpT[r*DG + j];
        sz[j] = z;
    }
    __syncthreads();
    {
        float zv = (j < DG) ? sz[j] : 0.f;
        float s = zv;
#pragma unroll
        for (int off = 16; off; off >>= 1) s += __shfl_xor_sync(0xffffffffu, s, off);
        if ((j & 31) == 0) sred[j >> 5] = s;
        __syncthreads();
    }
    float meanz = (sred[0]+sred[1]+sred[2]+sred[3]+sred[4]+sred[5]+sred[6]+sred[7]) * (1.f/DG);
    if (j < NL1) {
        float dz = 0.f, cs = 0.f, nn = 0.f;
        const float* cr = cb1 + j*DG;
        for (int r = 0; r < DG; r++) {
            float cv = cr[r];
            dz += sz[r]*cv; cs += cv; nn += cv*cv;
        }
        slog[j] = (dz - meanz*cs) / fmaxf(sqrtf(nn), 1e-12f);
    }
    __syncthreads();
    if (j == 0) {
        float best = slog[0]; int bi = 0;
        for (int t = 1; t < NL1; t++) if (slog[t] > best) { best = slog[t]; bi = t; }
        g_idx1[b] = bi;
    }
}

// -------- fp32 FFMA SGEMM: u = x @ Wl1.T + bl1 --------
// M=32768, N=256, K=1024; 128x64 tiles, 256 thr, 8x4/thread, occ 3
__global__ __launch_bounds__(256, 3)
void k_sgemm(const float* __restrict__ A, const float* __restrict__ Bm,
             const float* __restrict__ bias) {
    __shared__ float As[2][16][128];
    __shared__ float Bs[2][16][64];
    const int K = DIN;
    int tid = threadIdx.x;
    int alr = tid >> 1, alk = (tid & 1) << 3;
    int blr = tid >> 2, blk = (tid & 3) << 2;
    const float* Ap = A  + (size_t)(blockIdx.y * 128 + alr) * K + alk;
    const float* Bp = Bm + (size_t)(blockIdx.x * 64 + blr) * K + blk;
    int tx = tid & 15, ty = tid >> 4;
    int ar0 = ty * 4, ar1 = 64 + ty * 4;
    int bc0 = tx * 4;
    float acc[8][4];
#pragma unroll
    for (int i = 0; i < 8; i++)
#pragma unroll
        for (int jj = 0; jj < 4; jj++) acc[i][jj] = 0.f;

    float4 ra0, ra1, rb0;
    ra0 = *(const float4*)(Ap);
    ra1 = *(const float4*)(Ap + 4);
    rb0 = *(const float4*)(Bp);
    As[0][alk+0][alr] = ra0.x; As[0][alk+1][alr] = ra0.y;
    As[0][alk+2][alr] = ra0.z; As[0][alk+3][alr] = ra0.w;
    As[0][alk+4][alr] = ra1.x; As[0][alk+5][alr] = ra1.y;
    As[0][alk+6][alr] = ra1.z; As[0][alk+7][alr] = ra1.w;
    Bs[0][blk+0][blr] = rb0.x; Bs[0][blk+1][blr] = rb0.y;
    Bs[0][blk+2][blr] = rb0.z; Bs[0][blk+3][blr] = rb0.w;
    __syncthreads();

    for (int kt = 0; kt < 64; kt++) {
        int cur = kt & 1;
        if (kt < 63) {
            int ko = (kt + 1) * 16;
            ra0 = *(const float4*)(Ap + ko);
            ra1 = *(const float4*)(Ap + ko + 4);
            rb0 = *(const float4*)(Bp + ko);
        }
#pragma unroll
        for (int kk = 0; kk < 16; kk++) {
            float4 fa0 = *(const float4*)&As[cur][kk][ar0];
            float4 fa1 = *(const float4*)&As[cur][kk][ar1];
            float4 fb0 = *(const float4*)&Bs[cur][kk][bc0];
            float av[8] = {fa0.x, fa0.y, fa0.z, fa0.w, fa1.x, fa1.y, fa1.z, fa1.w};
            float bv[4] = {fb0.x, fb0.y, fb0.z, fb0.w};
#pragma unroll
            for (int i = 0; i < 8; i++)
#pragma unroll
                for (int jj = 0; jj < 4; jj++) acc[i][jj] += av[i] * bv[jj];
        }
        if (kt < 63) {
            int nxt = cur ^ 1;
            As[nxt][alk+0][alr] = ra0.x; As[nxt][alk+1][alr] = ra0.y;
            As[nxt][alk+2][alr] = ra0.z; As[nxt][alk+3][alr] = ra0.w;
            As[nxt][alk+4][alr] = ra1.x; As[nxt][alk+5][alr] = ra1.y;
            As[nxt][alk+6][alr] = ra1.z; As[nxt][alk+7][alr] = ra1.w;
            Bs[nxt][blk+0][blr] = rb0.x; Bs[nxt][blk+1][blr] = rb0.y;
            Bs[nxt][blk+2][blr] = rb0.z; Bs[nxt][blk+3][blr] = rb0.w;
            __syncthreads();
        }
    }
    int row0 = blockIdx.y * 128;
    int col0 = blockIdx.x * 64 + bc0;
    float4 bA = *(const float4*)(bias + col0);
#pragma unroll
    for (int i = 0; i < 8; i++) {
        int r = row0 + ((i < 4) ? (ar0 + i) : (ar1 + i - 4));
        float4 v0 = make_float4(acc[i][0] + bA.x, acc[i][1] + bA.y,
                                acc[i][2] + bA.z, acc[i][3] + bA.w);
        *(float4*)(g_U + (size_t)r * D + col0) = v0;
    }
}

__global__ __launch_bounds__(256)
void k_epilogue(float* __restrict__ out) {
    __shared__ float sM[D * NL2];
    __shared__ float sd[NL2];
    __shared__ int si1;
    int b = blockIdx.x;
    int tid = threadIdx.x;
    int lane = tid & 31;
    int w = tid >> 5;
    if (tid == 0) si1 = g_idx1[b];
    __syncthreads();
    int i1 = si1;
    {
        const float4* src = (const float4*)(g_Mall + (size_t)i1 * D * NL2);
        float4* dst = (float4*)sM;
        for (int t = tid; t < D * NL2 / 4; t += 256) dst[t] = src[t];
        if (tid < NL2) sd[tid] = g_dall[i1 * NL2 + tid];
    }
    __syncthreads();
    int rowBase = b * TLEN + blockIdx.y * 128 + w * 16;
    for (int r = 0; r < 16; r++) {
        int row = rowBase + r;
        const float4* up = (const float4*)(g_U + (size_t)row * D);
        float4 u0 = up[lane];
        float4 u1 = up[lane + 32];
        float h[8] = {u0.x, u0.y, u0.z, u0.w, u1.x, u1.y, u1.z, u1.w};
        float s = 0.f, q = 0.f;
#pragma unroll
        for (int e = 0; e < 8; e++) { s += h[e]; q += h[e]*h[e]; }
#pragma unroll
        for (int off = 16; off; off >>= 1) {
            s += __shfl_xor_sync(0xffffffffu, s, off);
            q += __shfl_xor_sync(0xffffffffu, q, off);
        }
        float mean = s * (1.f / 256.f);
        float var = q * (1.f / 256.f) - mean * mean;
        float rinv = rsqrtf(fmaxf(var, 0.f) + 1e-5f);
#pragma unroll
        for (int e = 0; e < 8; e++) h[e] = fmaxf((h[e] - mean) * rinv, 0.f);
        float acc = sd[lane];
#pragma unroll
        for (int e = 0; e < 8; e++) {
            int cb = (e < 4) ? e : (e + 124);
#pragma unroll 8
            for (int srcl = 0; srcl < 32; srcl++) {
                float hv = __shfl_sync(0xffffffffu, h[e], srcl);
                acc += hv * sM[(srcl * 4 + cb) * NL2 + lane];
            }
        }
        float best = acc; int bidx = lane;
#pragma unroll
        for (int off = 16; off; off >>= 1) {
            float ov = __shfl_xor_sync(0xffffffffu, best, off);
            int   oi = __shfl_xor_sync(0xffffffffu, bidx, off);
            if (ov > best || (ov == best && oi < bidx)) { best = ov; bidx = oi; }
        }
        const float4* trow = (const float4*)(g_table + (size_t)(i1 * NL2 + bidx) * D);
        float4* orow = (float4*)(out + (size_t)row * D);
        orow[lane]      = trow[lane];
        orow[lane + 32] = trow[lane + 32];
    }
}

extern "C" void kernel_launch(void* const* d_in, const int* in_sizes, int n_in,
                              void* d_out, int out_size) {
    const float* x   = (const float*)d_in[0];
    const float* Wg1 = (const float*)d_in[1];
    const float* bg1 = (const float*)d_in[2];
    const float* Wg2 = (const float*)d_in[3];
    const float* bg2 = (const float*)d_in[4];
    const float* Wl1 = (const float*)d_in[5];
    const float* bl1 = (const float*)d_in[6];
    const float* Wl2 = (const float*)d_in[7];
    const float* bl2 = (const float*)d_in[8];
    const float* Wp  = (const float*)d_in[9];
    const float* bp  = (const float*)d_in[10];
    const float* cb1 = (const float*)d_in[11];
    const float* Wtb = (const float*)d_in[12];
    const float* btb = (const float*)d_in[13];
    const float* Wfb = (const float*)d_in[14];
    const float* bfb = (const float*)d_in[15];
    const float* cb2 = (const float*)d_in[16];
    const float* Wf  = (const float*)d_in[17];
    const float* bf  = (const float*)d_in[18];
    float* out = (float*)d_out;

    static cudaStream_t s2 = 0;
    static cudaEvent_t eFork = 0, eJoin = 0;
    if (!s2) {
        cudaStreamCreateWithFlags(&s2, cudaStreamNonBlocking);
        cudaEventCreateWithFlags(&eFork, cudaEventDisableTiming);
        cudaEventCreateWithFlags(&eJoin, cudaEventDisableTiming);
    }

    // fork: side chain (independent of gemm) runs on s2, overlapping the gemm
    cudaEventRecord(eFork, 0);
    cudaStreamWaitEvent(s2, eFork, 0);

    // main stream: the big gemm starts immediately
    k_sgemm<<<dim3(4, 256), 256>>>(x, Wl1, bl1);

    // side chain on s2
    dim3 tb(32, 8);
    k_transpose_all<<<dim3(32, 8, 5), tb, 0, s2>>>(Wg1, Wg2, Wp, Wfb, Wf);
    k_wc   <<<64, 256, 0, s2>>>(Wtb, Wl2, bl2, btb);
    k_nck  <<<256, 64, 0, s2>>>(cb2);
    k_Md   <<<dim3(8, 32), 256, 0, s2>>>();
    k_table<<<256, 256, 0, s2>>>(cb2, bfb, cb1, bf);
    k_gs1  <<<256, 256, 0, s2>>>(x);
    k_gs2  <<<64, 256, 0, s2>>>();
    k_global<<<16, 256, 0, s2>>>(bg1, bg2, bp, cb1);
    cudaEventRecord(eJoin, s2);

    // join, then epilogue needs both g_U (main) and tables/idx1 (side)
    cudaStreamWaitEvent(0, eJoin, 0);
    k_epilogue<<<dim3(16, 16), 256>>>(out);
}